// round 10
// baseline (speedup 1.0000x reference)
#include <cuda_runtime.h>
#include <cuda_fp16.h>
#include <math.h>
#include <stdint.h>

// ---------------- problem constants ----------------
#define N0   4096
#define EDG  131072
#define K1   3277      // ceil(0.8*4096)
#define K2   2622      // ceil(0.8*3277)
#define K3   2098      // ceil(0.8*2622)
#define KP1  3328      // K1 padded to 128 (GEMM M/N tiles)
#define KP2  2688
#define KP3  2176
#define KD1  4096      // GEMM K dim padded to 64
#define KD2  3328
#define KD3  2624
#define CH   64
#define DSPLIT 32
#define RSPLIT 16

// ---------------- device scratch (no allocation allowed) ----------------
__device__ float g_A0[(size_t)N0*N0];
__device__ float g_A1[(size_t)K1*K1];
__device__ float g_A2[(size_t)K2*K2];
__device__ float g_A3[(size_t)K3*K3];
__device__ __half g_Ah[(size_t)KP1*KD1];   // GEMM operand A, [M,K] row-major
__device__ __half g_Bh[(size_t)KP1*KD1];   // GEMM operand B, [N,K] row-major
__device__ float g_x0[N0*CH];
__device__ float g_x1[K1*CH];
__device__ float g_x2[K2*CH];
__device__ float g_x3[K3*CH];
__device__ float g_xp[N0*CH];
__device__ float g_y [N0*CH];
__device__ float g_z [N0*CH];
__device__ float g_part [(size_t)RSPLIT*N0*CH];
__device__ float g_dpart[(size_t)DSPLIT*N0];
__device__ float g_disA[4][N0];
__device__ float g_slwA[4][N0];
__device__ float g_score[N0];
__device__ float g_sval[N0];
__device__ int   g_perm0[K1];
__device__ int   g_perm1[K2];
__device__ int   g_perm2[K3];
__device__ int   g_rnk[N0];

static inline int cdiv(int a, int b) { return (a + b - 1) / b; }

// ---------------- elementwise ----------------
__global__ void k_zero(float* p, int n) {
    int i = blockIdx.x * blockDim.x + threadIdx.x;
    if (i < n) p[i] = 0.f;
}

__global__ void k_edges(const int* __restrict__ src, const int* __restrict__ dst,
                        float* __restrict__ A) {
    int i = blockIdx.x * blockDim.x + threadIdx.x;
    if (i >= EDG) return;
    int s = src[i], d = dst[i];
    if (s != d) atomicAdd(&A[(size_t)s * N0 + d], 1.0f);   // exact integer adds
}

__global__ void k_diag1(float* A) {
    int i = blockIdx.x * blockDim.x + threadIdx.x;
    if (i < N0) A[(size_t)i * N0 + i] += 1.0f;
}

// ---------------- degree / normalization (computed ONCE per matrix) ----------------
__global__ void k_colsum(const float* __restrict__ A, int n, float* __restrict__ dpart) {
    int c = blockIdx.x * blockDim.x + threadIdx.x;
    if (c >= n) return;
    int chunk = (n + DSPLIT - 1) / DSPLIT;
    int r0 = blockIdx.y * chunk;
    int r1 = min(n, r0 + chunk);
    float s = 0.f;
    for (int r = r0; r < r1; r++) s += A[(size_t)r * n + c];
    dpart[(size_t)blockIdx.y * n + c] = s;
}

__global__ void k_degfin(const float* __restrict__ A, int n,
                         const float* __restrict__ dpart,
                         float* __restrict__ dis, float* __restrict__ slw) {
    int c = blockIdx.x * blockDim.x + threadIdx.x;
    if (c >= n) return;
    float s = 0.f;
    for (int q = 0; q < DSPLIT; q++) s += dpart[(size_t)q * n + c];
    float dg = A[(size_t)c * n + c];
    float sl = (dg == 0.f) ? 2.f : 0.f;    // add_remaining_self_loops, fill=2
    float deg = s + sl;
    slw[c] = sl;
    dis[c] = (deg > 0.f) ? rsqrtf(deg) : 0.f;
}

// ---------------- x @ W, scaled by dis ----------------
template<int CIN, int COUT>
__global__ void k_xw(const float* __restrict__ x, int n, const float* __restrict__ W,
                     const float* __restrict__ dis,
                     float* __restrict__ y, float* __restrict__ z) {
    int idx = blockIdx.x * blockDim.x + threadIdx.x;
    if (idx >= n * COUT) return;
    int r = idx / COUT, j = idx % COUT;
    float s = 0.f;
    #pragma unroll
    for (int k = 0; k < CIN; k++) s += x[(size_t)r * CIN + k] * W[k * COUT + j];
    y[idx] = s;
    z[idx] = dis[r] * s;
}

// ---------------- out_part = (A^T z) split over rows ----------------
template<int COUT>
__global__ void k_atzp(const float* __restrict__ A, int n,
                       const float* __restrict__ z, float* __restrict__ part) {
    const int RC = 8;
    __shared__ float zs[RC][COUT];
    int c = blockIdx.x * blockDim.x + threadIdx.x;
    int chunk = (n + RSPLIT - 1) / RSPLIT;
    int r0b = blockIdx.y * chunk;
    int r1  = min(n, r0b + chunk);
    float acc[COUT];
    #pragma unroll
    for (int j = 0; j < COUT; j++) acc[j] = 0.f;
    for (int r0 = r0b; r0 < r1; r0 += RC) {
        __syncthreads();
        for (int t = threadIdx.x; t < RC * COUT; t += blockDim.x) {
            int rr = t / COUT, j = t % COUT;
            int r = r0 + rr;
            zs[rr][j] = (r < r1) ? z[(size_t)r * COUT + j] : 0.f;
        }
        __syncthreads();
        int rmax = min(RC, r1 - r0);
        if (c < n) {
            for (int rr = 0; rr < rmax; rr++) {
                float a = A[(size_t)(r0 + rr) * n + c];
                #pragma unroll
                for (int j = 0; j < COUT; j++) acc[j] += a * zs[rr][j];
            }
        }
    }
    if (c < n) {
        #pragma unroll
        for (int j = 0; j < COUT; j++)
            part[((size_t)blockIdx.y * n + c) * COUT + j] = acc[j];
    }
}

template<int COUT>
__global__ void k_fin(int n, const float* __restrict__ part,
                      const float* __restrict__ y, const float* __restrict__ dis,
                      const float* __restrict__ slw, const float* __restrict__ b,
                      int doRelu, float* __restrict__ out) {
    int idx = blockIdx.x * blockDim.x + threadIdx.x;
    if (idx >= n * COUT) return;
    int c = idx / COUT, j = idx % COUT;
    float s = 0.f;
    for (int q = 0; q < RSPLIT; q++) s += part[((size_t)q * n + c) * COUT + j];
    float dc = dis[c];
    float v = dc * (s + slw[c] * dc * y[idx]) + b[j];
    if (doRelu) v = fmaxf(v, 0.f);
    out[idx] = v;
}

// ---------------- top-k pooling ----------------
__global__ void k_score(const float* __restrict__ x, int n,
                        const float* __restrict__ p, float* __restrict__ s) {
    int r = blockIdx.x * blockDim.x + threadIdx.x;
    if (r >= n) return;
    float pp = 0.f, dot = 0.f;
    #pragma unroll
    for (int k = 0; k < CH; k++) {
        float pk = p[k];
        pp += pk * pk;
        dot += x[(size_t)r * CH + k] * pk;
    }
    s[r] = tanhf(dot / sqrtf(pp));
}

// Fused: rank + perm + sval + inverse-perm + pooled features
// rank = #{j : s[j] > s[i]  ||  (s[j]==s[i] && j<i)}  -> matches lax.top_k order
__global__ void k_rank2(const float* __restrict__ score, int n, int k,
                        int* __restrict__ perm, float* __restrict__ sval,
                        int* __restrict__ rnk,
                        const float* __restrict__ x, float* __restrict__ xp) {
    __shared__ float ss[1024];
    int i = blockIdx.x * blockDim.x + threadIdx.x;
    float si = (i < n) ? score[i] : 0.f;
    int rank = 0;
    for (int j0 = 0; j0 < n; j0 += 1024) {
        int cnt = min(1024, n - j0);
        __syncthreads();
        for (int t = threadIdx.x; t < cnt; t += blockDim.x) ss[t] = score[j0 + t];
        __syncthreads();
        if (i < n) {
            for (int jj = 0; jj < cnt; jj++) {
                float sj = ss[jj];
                int j = j0 + jj;
                rank += (sj > si) || (sj == si && j < i);
            }
        }
    }
    if (i < n) {
        if (rank < k) {
            perm[rank] = i;
            sval[rank] = si;
            rnk[i] = rank;
            const float4* xr = (const float4*)(x + (size_t)i * CH);
            float4* xo = (float4*)(xp + (size_t)rank * CH);
            #pragma unroll
            for (int q = 0; q < CH / 4; q++) {
                float4 v = xr[q];
                v.x *= si; v.y *= si; v.z *= si; v.w *= si;
                xo[q] = v;
            }
        } else {
            rnk[i] = -1;
        }
    }
}

// ---------------- gathers -> fp16 GEMM operands ----------------
// A operand [kp x kd]: Aop[r][kk] = A1[perm[r], kk]   (A1 = unit diag, A off-diag)
__global__ void k_gA(const float* __restrict__ A, int n, const int* __restrict__ perm,
                     int k, int kd, __half* __restrict__ H) {
    size_t idx = (size_t)blockIdx.x * blockDim.x + threadIdx.x;
    int r = (int)(idx / kd), kk = (int)(idx % kd);
    float v = 0.f;
    if (r < k && kk < n) {
        int pr = perm[r];
        v = (kk == pr) ? 1.0f : A[(size_t)pr * n + kk];
    }
    H[idx] = __float2half(v);   // small integers: exact
}

// B operand [kpN x kd] via 32x32 tiled transpose-gather (coalesced both sides):
// Bop[rnk[j]][kk] = A1[kk][j]; grid.y spans kd so K-padding columns get zeros.
__global__ void k_gBt(const float* __restrict__ A, int n, const int* __restrict__ rnk,
                      int kd, __half* __restrict__ H) {
    __shared__ float t[32][33];
    int j0 = blockIdx.x * 32, k0 = blockIdx.y * 32;
    int tx = threadIdx.x, ty = threadIdx.y;   // 32 x 8
    #pragma unroll
    for (int i = 0; i < 32; i += 8) {
        int kk = k0 + ty + i, j = j0 + tx;
        float v = 0.f;
        if (kk < n && j < n) v = (kk == j) ? 1.0f : A[(size_t)kk * n + j];
        t[ty + i][tx] = v;
    }
    __syncthreads();
    #pragma unroll
    for (int i = 0; i < 32; i += 8) {
        int j = j0 + ty + i, kk = k0 + tx;
        if (j < n && kk < kd) {
            int r = rnk[j];
            if (r >= 0) H[(size_t)r * kd + kk] = __float2half(t[tx][ty + i]);
        }
    }
}

// ---------------- mma.sync fp16 GEMM: C = A @ B^T, 128x128 tile ----------------
#define BM 128
#define BN 128
#define BK 64
#define STG 3
#define LDS_H 72                      // padded halves/row: 144B = 9 x 16B
#define STAGE_HALVES (2 * 128 * LDS_H)
#define SMEM_HGEMM (STG * STAGE_HALVES * 2)   // 110592 bytes -> 2 CTAs/SM

__device__ __forceinline__ uint32_t smem_u32(const void* p) {
    uint32_t a;
    asm("{ .reg .u64 t; cvta.to.shared.u64 t, %1; cvt.u32.u64 %0, t; }"
        : "=r"(a) : "l"(p));
    return a;
}
__device__ __forceinline__ void cpa16(uint32_t s, const void* g) {
    asm volatile("cp.async.cg.shared.global [%0], [%1], 16;" :: "r"(s), "l"(g));
}
#define CP_COMMIT() asm volatile("cp.async.commit_group;" ::: "memory")
#define CP_WAIT(n)  asm volatile("cp.async.wait_group %0;" :: "n"(n) : "memory")

__device__ __forceinline__ void ldm_x4(uint32_t* r, uint32_t addr) {
    asm volatile("ldmatrix.sync.aligned.m8n8.x4.shared.b16 {%0,%1,%2,%3}, [%4];"
        : "=r"(r[0]), "=r"(r[1]), "=r"(r[2]), "=r"(r[3]) : "r"(addr));
}
__device__ __forceinline__ void mma16816(float* d, const uint32_t* a,
                                         uint32_t b0, uint32_t b1) {
    asm volatile("mma.sync.aligned.m16n8k16.row.col.f32.f16.f16.f32 "
        "{%0,%1,%2,%3}, {%4,%5,%6,%7}, {%8,%9}, {%0,%1,%2,%3};"
        : "+f"(d[0]), "+f"(d[1]), "+f"(d[2]), "+f"(d[3])
        : "r"(a[0]), "r"(a[1]), "r"(a[2]), "r"(a[3]), "r"(b0), "r"(b1));
}

__global__ __launch_bounds__(256, 2) void k_hgemm(
    int mreal, int nreal, int kd,
    const __half* __restrict__ Ap, const __half* __restrict__ Bp,
    float* __restrict__ C, int ldc, int zeroDiag)
{
    extern __shared__ __half sh[];
    const int tid = threadIdx.x;
    const int wid = tid >> 5, lane = tid & 31;
    const int bm = blockIdx.y * BM, bn = blockIdx.x * BN;
    const int wm0 = (wid & 3) * 32, wn0 = (wid >> 2) * 64;
    const int nch = kd / BK;

    const __half* Ag = Ap + (size_t)bm * kd;
    const __half* Bg = Bp + (size_t)bn * kd;

    const int lc8 = tid & 7;          // 16B column within 64-half chunk
    const int lr0 = tid >> 3;         // base row

    float acc[2][8][4];
    #pragma unroll
    for (int mt = 0; mt < 2; mt++)
        #pragma unroll
        for (int n8 = 0; n8 < 8; n8++)
            #pragma unroll
            for (int q = 0; q < 4; q++) acc[mt][n8][q] = 0.f;

    // prologue: stages 0..STG-2
    #pragma unroll
    for (int s = 0; s < STG - 1; s++) {
        __half* sA = sh + s * STAGE_HALVES;
        __half* sB = sA + 128 * LDS_H;
        const __half* Asrc = Ag + s * BK;
        const __half* Bsrc = Bg + s * BK;
        #pragma unroll
        for (int i = 0; i < 4; i++) {
            int row = lr0 + i * 32;
            cpa16(smem_u32(&sA[row * LDS_H + lc8 * 8]), Asrc + (size_t)row * kd + lc8 * 8);
            cpa16(smem_u32(&sB[row * LDS_H + lc8 * 8]), Bsrc + (size_t)row * kd + lc8 * 8);
        }
        CP_COMMIT();
    }

    const int ar = wm0 + (lane & 15);
    const int ac = (lane >> 4) * 8;
    const int br = wn0 + (lane & 7) + ((lane >> 4) & 1) * 8;
    const int bc = ((lane >> 3) & 1) * 8;

    for (int c = 0; c < nch; c++) {
        CP_WAIT(STG - 2);
        __syncthreads();

        // prefetch chunk c+STG-1
        {
            int cf = c + STG - 1;
            if (cf < nch) {
                int s = cf % STG;
                __half* sA = sh + s * STAGE_HALVES;
                __half* sB = sA + 128 * LDS_H;
                const __half* Asrc = Ag + cf * BK;
                const __half* Bsrc = Bg + cf * BK;
                #pragma unroll
                for (int i = 0; i < 4; i++) {
                    int row = lr0 + i * 32;
                    cpa16(smem_u32(&sA[row * LDS_H + lc8 * 8]),
                          Asrc + (size_t)row * kd + lc8 * 8);
                    cpa16(smem_u32(&sB[row * LDS_H + lc8 * 8]),
                          Bsrc + (size_t)row * kd + lc8 * 8);
                }
            }
            CP_COMMIT();
        }

        // compute on stage c % STG, register-double-buffered across k16
        {
            int s = c % STG;
            const __half* sA = sh + s * STAGE_HALVES;
            const __half* sB = sA + 128 * LDS_H;
            uint32_t a[2][2][4], b[2][4][4];
            // preload k16 = 0 into buffer 0
            #pragma unroll
            for (int mt = 0; mt < 2; mt++)
                ldm_x4(a[0][mt], smem_u32(&sA[(ar + mt * 16) * LDS_H + ac]));
            #pragma unroll
            for (int ng = 0; ng < 4; ng++)
                ldm_x4(b[0][ng], smem_u32(&sB[(br + ng * 16) * LDS_H + bc]));
            #pragma unroll
            for (int k16 = 0; k16 < 4; k16++) {
                int cur = k16 & 1, nxt = cur ^ 1;
                if (k16 < 3) {
                    #pragma unroll
                    for (int mt = 0; mt < 2; mt++)
                        ldm_x4(a[nxt][mt],
                               smem_u32(&sA[(ar + mt * 16) * LDS_H + (k16 + 1) * 16 + ac]));
                    #pragma unroll
                    for (int ng = 0; ng < 4; ng++)
                        ldm_x4(b[nxt][ng],
                               smem_u32(&sB[(br + ng * 16) * LDS_H + (k16 + 1) * 16 + bc]));
                }
                #pragma unroll
                for (int mt = 0; mt < 2; mt++)
                    #pragma unroll
                    for (int n8 = 0; n8 < 8; n8++) {
                        int ng = n8 >> 1, hi = (n8 & 1) << 1;
                        mma16816(acc[mt][n8], a[cur][mt], b[cur][ng][hi], b[cur][ng][hi + 1]);
                    }
            }
        }
        __syncthreads();
    }

    // epilogue: direct coalesced stores (8x8 patches -> 8 full 32B sectors)
    int g = lane >> 2, tg = lane & 3;
    #pragma unroll
    for (int mt = 0; mt < 2; mt++) {
        #pragma unroll
        for (int n8 = 0; n8 < 8; n8++) {
            int r1 = bm + wm0 + mt * 16 + g;
            int r2 = r1 + 8;
            int c0 = bn + wn0 + n8 * 8 + tg * 2;
            float* a4 = acc[mt][n8];
            if (r1 < mreal) {
                if (c0 < nreal)
                    C[(size_t)r1 * ldc + c0] = (zeroDiag && r1 == c0) ? 0.f : a4[0];
                if (c0 + 1 < nreal)
                    C[(size_t)r1 * ldc + c0 + 1] = (zeroDiag && r1 == c0 + 1) ? 0.f : a4[1];
            }
            if (r2 < mreal) {
                if (c0 < nreal)
                    C[(size_t)r2 * ldc + c0] = (zeroDiag && r2 == c0) ? 0.f : a4[2];
                if (c0 + 1 < nreal)
                    C[(size_t)r2 * ldc + c0 + 1] = (zeroDiag && r2 == c0 + 1) ? 0.f : a4[3];
            }
        }
    }
}

// ---------------- unpool: res[perm[r]] += xup[r] ----------------
__global__ void k_unpool(float* __restrict__ res, const float* __restrict__ xup,
                         const int* __restrict__ perm, int k) {
    int idx = blockIdx.x * blockDim.x + threadIdx.x;
    if (idx >= k * CH) return;
    int r = idx / CH, j = idx % CH;
    res[(size_t)perm[r] * CH + j] += xup[idx];
}

// ---------------- host orchestration ----------------
struct DevPtrs {
    float *A0, *A1, *A2, *A3;
    __half *Ah, *Bh;
    float *x0, *x1, *x2, *x3, *xp, *y, *z, *part, *dpart, *score, *sval;
    float *dis[4], *slw[4];
    int *perm0, *perm1, *perm2, *rnk;
};
static DevPtrs P;
static bool g_init = false;

static void prep_deg(const float* A, int n, int lvl) {
    dim3 cs(cdiv(n, 256), DSPLIT);
    k_colsum<<<cs, 256>>>(A, n, P.dpart);
    k_degfin<<<cdiv(n, 256), 256>>>(A, n, P.dpart, P.dis[lvl], P.slw[lvl]);
}

template<int CIN, int COUT>
static void gcn(const float* A, int n, int lvl, const float* xin, const float* W,
                const float* b, bool relu, float* out) {
    k_xw<CIN, COUT><<<cdiv(n * COUT, 256), 256>>>(xin, n, W, P.dis[lvl], P.y, P.z);
    dim3 ag(cdiv(n, 256), RSPLIT);
    k_atzp<COUT><<<ag, 256>>>(A, n, P.z, P.part);
    k_fin<COUT><<<cdiv(n * COUT, 256), 256>>>(n, P.part, P.y, P.dis[lvl], P.slw[lvl],
                                              b, relu ? 1 : 0, out);
}

static void pool_level(const float* A, int n, int k, int kp, int kd,
                       const float* x, const float* p, int* perm, float* Anext) {
    k_score<<<cdiv(n, 256), 256>>>(x, n, p, P.score);
    k_rank2<<<cdiv(n, 256), 256>>>(P.score, n, k, perm, P.sval, P.rnk, x, P.xp);
    // A operand: row gather (coalesced)
    size_t tot = (size_t)kp * kd;
    k_gA<<<(int)((tot + 255) / 256), 256>>>(A, n, perm, k, kd, P.Ah);
    // B operand: tiled transpose-gather (coalesced), grid.y spans kd for padding
    dim3 tg(cdiv(n, 32), cdiv(kd, 32));
    k_gBt<<<tg, dim3(32, 8)>>>(A, n, P.rnk, kd, P.Bh);
    dim3 gg(kp / 128, kp / 128);
    k_hgemm<<<gg, 256, SMEM_HGEMM>>>(k, k, kd, P.Ah, P.Bh, Anext, k, 1);
}

extern "C" void kernel_launch(void* const* d_in, const int* in_sizes, int n_in,
                              void* d_out, int out_size) {
    if (!g_init) {
        cudaGetSymbolAddress((void**)&P.A0, g_A0);
        cudaGetSymbolAddress((void**)&P.A1, g_A1);
        cudaGetSymbolAddress((void**)&P.A2, g_A2);
        cudaGetSymbolAddress((void**)&P.A3, g_A3);
        cudaGetSymbolAddress((void**)&P.Ah, g_Ah);
        cudaGetSymbolAddress((void**)&P.Bh, g_Bh);
        cudaGetSymbolAddress((void**)&P.x0, g_x0);
        cudaGetSymbolAddress((void**)&P.x1, g_x1);
        cudaGetSymbolAddress((void**)&P.x2, g_x2);
        cudaGetSymbolAddress((void**)&P.x3, g_x3);
        cudaGetSymbolAddress((void**)&P.xp, g_xp);
        cudaGetSymbolAddress((void**)&P.y,  g_y);
        cudaGetSymbolAddress((void**)&P.z,  g_z);
        cudaGetSymbolAddress((void**)&P.part,  g_part);
        cudaGetSymbolAddress((void**)&P.dpart, g_dpart);
        float* disBase; float* slwBase;
        cudaGetSymbolAddress((void**)&disBase, g_disA);
        cudaGetSymbolAddress((void**)&slwBase, g_slwA);
        for (int l = 0; l < 4; l++) { P.dis[l] = disBase + l * N0; P.slw[l] = slwBase + l * N0; }
        cudaGetSymbolAddress((void**)&P.score, g_score);
        cudaGetSymbolAddress((void**)&P.sval,  g_sval);
        cudaGetSymbolAddress((void**)&P.perm0, g_perm0);
        cudaGetSymbolAddress((void**)&P.perm1, g_perm1);
        cudaGetSymbolAddress((void**)&P.perm2, g_perm2);
        cudaGetSymbolAddress((void**)&P.rnk,   g_rnk);
        cudaFuncSetAttribute(k_hgemm, cudaFuncAttributeMaxDynamicSharedMemorySize,
                             SMEM_HGEMM);
        g_init = true;
    }

    const float* x_in = (const float*)d_in[0];
    const int*   ei   = (const int*)d_in[1];
    const float* W0 = (const float*)d_in[2];  const float* b0 = (const float*)d_in[3];
    const float* W1 = (const float*)d_in[4];  const float* b1 = (const float*)d_in[5];
    const float* W2 = (const float*)d_in[6];  const float* b2 = (const float*)d_in[7];
    const float* W3 = (const float*)d_in[8];  const float* b3 = (const float*)d_in[9];
    const float* p1 = (const float*)d_in[10];
    const float* p2 = (const float*)d_in[11];
    const float* p3 = (const float*)d_in[12];
    const float* U0 = (const float*)d_in[13]; const float* c0 = (const float*)d_in[14];
    const float* U1 = (const float*)d_in[15]; const float* c1 = (const float*)d_in[16];
    const float* U2 = (const float*)d_in[17]; const float* c2 = (const float*)d_in[18];
    float* out = (float*)d_out;

    // A0 = dense adjacency with parallel-edge accumulation + unit self loops
    k_zero<<<cdiv(N0 * N0, 256), 256>>>(P.A0, N0 * N0);
    k_edges<<<cdiv(EDG, 256), 256>>>(ei, ei + EDG, P.A0);
    k_diag1<<<cdiv(N0, 256), 256>>>(P.A0);

    // ---- down path ----
    prep_deg(P.A0, N0, 0);
    gcn<20, 64>(P.A0, N0, 0, x_in, W0, b0, true, P.x0);

    pool_level(P.A0, N0, K1, KP1, KD1, P.x0, p1, P.perm0, P.A1);
    prep_deg(P.A1, K1, 1);
    gcn<64, 64>(P.A1, K1, 1, P.xp, W1, b1, true, P.x1);

    pool_level(P.A1, K1, K2, KP2, KD2, P.x1, p2, P.perm1, P.A2);
    prep_deg(P.A2, K2, 2);
    gcn<64, 64>(P.A2, K2, 2, P.xp, W2, b2, true, P.x2);

    pool_level(P.A2, K2, K3, KP3, KD3, P.x2, p3, P.perm2, P.A3);
    prep_deg(P.A3, K3, 3);
    gcn<64, 64>(P.A3, K3, 3, P.xp, W3, b3, true, P.x3);

    // ---- up path (degrees reused from down path) ----
    k_unpool<<<cdiv(K3 * CH, 256), 256>>>(P.x2, P.x3, P.perm2, K3);
    gcn<64, 64>(P.A2, K2, 2, P.x2, U0, c0, true, P.xp);

    k_unpool<<<cdiv(K2 * CH, 256), 256>>>(P.x1, P.xp, P.perm1, K2);
    gcn<64, 64>(P.A1, K1, 1, P.x1, U1, c1, true, P.xp);

    k_unpool<<<cdiv(K1 * CH, 256), 256>>>(P.x0, P.xp, P.perm0, K1);
    gcn<64, 20>(P.A0, N0, 0, P.x0, U2, c2, false, out);
}

// round 12
// speedup vs baseline: 1.0067x; 1.0067x over previous
#include <cuda_runtime.h>
#include <cuda_fp16.h>
#include <math.h>
#include <stdint.h>

// ---------------- problem constants ----------------
#define N0   4096
#define EDG  131072
#define K1   3277      // ceil(0.8*4096)
#define K2   2622      // ceil(0.8*3277)
#define K3   2098      // ceil(0.8*2622)
#define KP1  3328      // K1 padded to 128 (GEMM M/N tiles)
#define KP2  2688
#define KP3  2176
#define KD1  4096      // GEMM K dim padded to 64
#define KD2  3328
#define KD3  2624
#define CH   64
#define DSPLIT 32
#define RSPLIT 16

// ---------------- device scratch (no allocation allowed) ----------------
__device__ float g_A0[(size_t)N0*N0];
__device__ float g_A1[(size_t)K1*K1];
__device__ float g_A2[(size_t)K2*K2];
__device__ float g_A3[(size_t)K3*K3];
__device__ __half g_Ah[(size_t)KP1*KD1];   // GEMM operand A, [M,K] row-major
__device__ __half g_Bh[(size_t)KP1*KD1];   // GEMM operand B, [N,K] row-major
__device__ float g_x0[N0*CH];
__device__ float g_x1[K1*CH];
__device__ float g_x2[K2*CH];
__device__ float g_x3[K3*CH];
__device__ float g_xp[N0*CH];
__device__ float g_y [N0*CH];
__device__ float g_z [N0*CH];
__device__ float g_part [(size_t)RSPLIT*N0*CH];
__device__ float g_dpart[(size_t)DSPLIT*N0];
__device__ float g_disA[4][N0];
__device__ float g_slwA[4][N0];
__device__ float g_score[N0];
__device__ float g_sval[N0];
__device__ int   g_perm0[K1];
__device__ int   g_perm1[K2];
__device__ int   g_perm2[K3];
__device__ int   g_rnk[N0];

static inline int cdiv(int a, int b) { return (a + b - 1) / b; }

// ---------------- elementwise ----------------
__global__ void k_zero(float* p, int n) {
    int i = blockIdx.x * blockDim.x + threadIdx.x;
    if (i < n) p[i] = 0.f;
}

__global__ void k_edges(const int* __restrict__ src, const int* __restrict__ dst,
                        float* __restrict__ A) {
    int i = blockIdx.x * blockDim.x + threadIdx.x;
    if (i >= EDG) return;
    int s = src[i], d = dst[i];
    if (s != d) atomicAdd(&A[(size_t)s * N0 + d], 1.0f);   // exact integer adds
}

__global__ void k_diag1(float* A) {
    int i = blockIdx.x * blockDim.x + threadIdx.x;
    if (i < N0) A[(size_t)i * N0 + i] += 1.0f;
}

// ---------------- degree / normalization (computed ONCE per matrix) ----------------
__global__ void k_colsum(const float* __restrict__ A, int n, float* __restrict__ dpart) {
    int c = blockIdx.x * blockDim.x + threadIdx.x;
    if (c >= n) return;
    int chunk = (n + DSPLIT - 1) / DSPLIT;
    int r0 = blockIdx.y * chunk;
    int r1 = min(n, r0 + chunk);
    float s = 0.f;
    for (int r = r0; r < r1; r++) s += A[(size_t)r * n + c];
    dpart[(size_t)blockIdx.y * n + c] = s;
}

__global__ void k_degfin(const float* __restrict__ A, int n,
                         const float* __restrict__ dpart,
                         float* __restrict__ dis, float* __restrict__ slw) {
    int c = blockIdx.x * blockDim.x + threadIdx.x;
    if (c >= n) return;
    float s = 0.f;
    for (int q = 0; q < DSPLIT; q++) s += dpart[(size_t)q * n + c];
    float dg = A[(size_t)c * n + c];
    float sl = (dg == 0.f) ? 2.f : 0.f;    // add_remaining_self_loops, fill=2
    float deg = s + sl;
    slw[c] = sl;
    dis[c] = (deg > 0.f) ? rsqrtf(deg) : 0.f;
}

// ---------------- x @ W, scaled by dis ----------------
template<int CIN, int COUT>
__global__ void k_xw(const float* __restrict__ x, int n, const float* __restrict__ W,
                     const float* __restrict__ dis,
                     float* __restrict__ y, float* __restrict__ z) {
    int idx = blockIdx.x * blockDim.x + threadIdx.x;
    if (idx >= n * COUT) return;
    int r = idx / COUT, j = idx % COUT;
    float s = 0.f;
    #pragma unroll
    for (int k = 0; k < CIN; k++) s += x[(size_t)r * CIN + k] * W[k * COUT + j];
    y[idx] = s;
    z[idx] = dis[r] * s;
}

// ---------------- out_part = (A^T z) split over rows ----------------
template<int COUT>
__global__ void k_atzp(const float* __restrict__ A, int n,
                       const float* __restrict__ z, float* __restrict__ part) {
    const int RC = 8;
    __shared__ float zs[RC][COUT];
    int c = blockIdx.x * blockDim.x + threadIdx.x;
    int chunk = (n + RSPLIT - 1) / RSPLIT;
    int r0b = blockIdx.y * chunk;
    int r1  = min(n, r0b + chunk);
    float acc[COUT];
    #pragma unroll
    for (int j = 0; j < COUT; j++) acc[j] = 0.f;
    for (int r0 = r0b; r0 < r1; r0 += RC) {
        __syncthreads();
        for (int t = threadIdx.x; t < RC * COUT; t += blockDim.x) {
            int rr = t / COUT, j = t % COUT;
            int r = r0 + rr;
            zs[rr][j] = (r < r1) ? z[(size_t)r * COUT + j] : 0.f;
        }
        __syncthreads();
        int rmax = min(RC, r1 - r0);
        if (c < n) {
            for (int rr = 0; rr < rmax; rr++) {
                float a = A[(size_t)(r0 + rr) * n + c];
                #pragma unroll
                for (int j = 0; j < COUT; j++) acc[j] += a * zs[rr][j];
            }
        }
    }
    if (c < n) {
        #pragma unroll
        for (int j = 0; j < COUT; j++)
            part[((size_t)blockIdx.y * n + c) * COUT + j] = acc[j];
    }
}

template<int COUT>
__global__ void k_fin(int n, const float* __restrict__ part,
                      const float* __restrict__ y, const float* __restrict__ dis,
                      const float* __restrict__ slw, const float* __restrict__ b,
                      int doRelu, float* __restrict__ out) {
    int idx = blockIdx.x * blockDim.x + threadIdx.x;
    if (idx >= n * COUT) return;
    int c = idx / COUT, j = idx % COUT;
    float s = 0.f;
    for (int q = 0; q < RSPLIT; q++) s += part[((size_t)q * n + c) * COUT + j];
    float dc = dis[c];
    float v = dc * (s + slw[c] * dc * y[idx]) + b[j];
    if (doRelu) v = fmaxf(v, 0.f);
    out[idx] = v;
}

// ---------------- top-k pooling ----------------
__global__ void k_score(const float* __restrict__ x, int n,
                        const float* __restrict__ p, float* __restrict__ s) {
    int r = blockIdx.x * blockDim.x + threadIdx.x;
    if (r >= n) return;
    float pp = 0.f, dot = 0.f;
    #pragma unroll
    for (int k = 0; k < CH; k++) {
        float pk = p[k];
        pp += pk * pk;
        dot += x[(size_t)r * CH + k] * pk;
    }
    s[r] = tanhf(dot / sqrtf(pp));
}

// Fused: rank + perm + sval + inverse-perm + pooled features
// rank = #{j : s[j] > s[i]  ||  (s[j]==s[i] && j<i)}  -> matches lax.top_k order
__global__ void k_rank2(const float* __restrict__ score, int n, int k,
                        int* __restrict__ perm, float* __restrict__ sval,
                        int* __restrict__ rnk,
                        const float* __restrict__ x, float* __restrict__ xp) {
    __shared__ float ss[1024];
    int i = blockIdx.x * blockDim.x + threadIdx.x;
    float si = (i < n) ? score[i] : 0.f;
    int rank = 0;
    for (int j0 = 0; j0 < n; j0 += 1024) {
        int cnt = min(1024, n - j0);
        __syncthreads();
        for (int t = threadIdx.x; t < cnt; t += blockDim.x) ss[t] = score[j0 + t];
        __syncthreads();
        if (i < n) {
            for (int jj = 0; jj < cnt; jj++) {
                float sj = ss[jj];
                int j = j0 + jj;
                rank += (sj > si) || (sj == si && j < i);
            }
        }
    }
    if (i < n) {
        if (rank < k) {
            perm[rank] = i;
            sval[rank] = si;
            rnk[i] = rank;
            const float4* xr = (const float4*)(x + (size_t)i * CH);
            float4* xo = (float4*)(xp + (size_t)rank * CH);
            #pragma unroll
            for (int q = 0; q < CH / 4; q++) {
                float4 v = xr[q];
                v.x *= si; v.y *= si; v.z *= si; v.w *= si;
                xo[q] = v;
            }
        } else {
            rnk[i] = -1;
        }
    }
}

// ---------------- gathers -> fp16 GEMM operands ----------------
// A operand [kp x kd]: Aop[r][kk] = A1[perm[r], kk]   (A1 = unit diag, A off-diag)
__global__ void k_gA(const float* __restrict__ A, int n, const int* __restrict__ perm,
                     int k, int kd, __half* __restrict__ H) {
    size_t idx = (size_t)blockIdx.x * blockDim.x + threadIdx.x;
    int r = (int)(idx / kd), kk = (int)(idx % kd);
    float v = 0.f;
    if (r < k && kk < n) {
        int pr = perm[r];
        v = (kk == pr) ? 1.0f : A[(size_t)pr * n + kk];
    }
    H[idx] = __float2half(v);   // small integers: exact
}

// B operand [kpN x kd] via 32x32 tiled transpose-gather (coalesced both sides):
// Bop[rnk[j]][kk] = A1[kk][j]; grid.y spans kd so K-padding columns get zeros.
__global__ void k_gBt(const float* __restrict__ A, int n, const int* __restrict__ rnk,
                      int kd, __half* __restrict__ H) {
    __shared__ float t[32][33];
    int j0 = blockIdx.x * 32, k0 = blockIdx.y * 32;
    int tx = threadIdx.x, ty = threadIdx.y;   // 32 x 8
    #pragma unroll
    for (int i = 0; i < 32; i += 8) {
        int kk = k0 + ty + i, j = j0 + tx;
        float v = 0.f;
        if (kk < n && j < n) v = (kk == j) ? 1.0f : A[(size_t)kk * n + j];
        t[ty + i][tx] = v;
    }
    __syncthreads();
    #pragma unroll
    for (int i = 0; i < 32; i += 8) {
        int j = j0 + ty + i, kk = k0 + tx;
        if (j < n && kk < kd) {
            int r = rnk[j];
            if (r >= 0) H[(size_t)r * kd + kk] = __float2half(t[tx][ty + i]);
        }
    }
}

// ---------------- mma.sync fp16 GEMM: C = A @ B^T, 128x128 tile ----------------
#define BM 128
#define BN 128
#define BK 64
#define STG 3
#define LDS_H 72                      // padded halves/row: 144B = 9 x 16B
#define STAGE_HALVES (2 * 128 * LDS_H)
#define SMEM_HGEMM (STG * STAGE_HALVES * 2)   // 110592 bytes -> 2 CTAs/SM

__device__ __forceinline__ uint32_t smem_u32(const void* p) {
    uint32_t a;
    asm("{ .reg .u64 t; cvta.to.shared.u64 t, %1; cvt.u32.u64 %0, t; }"
        : "=r"(a) : "l"(p));
    return a;
}
__device__ __forceinline__ void cpa16(uint32_t s, const void* g) {
    asm volatile("cp.async.cg.shared.global [%0], [%1], 16;" :: "r"(s), "l"(g));
}
#define CP_COMMIT() asm volatile("cp.async.commit_group;" ::: "memory")
#define CP_WAIT(n)  asm volatile("cp.async.wait_group %0;" :: "n"(n) : "memory")

__device__ __forceinline__ void ldm_x4(uint32_t* r, uint32_t addr) {
    asm volatile("ldmatrix.sync.aligned.m8n8.x4.shared.b16 {%0,%1,%2,%3}, [%4];"
        : "=r"(r[0]), "=r"(r[1]), "=r"(r[2]), "=r"(r[3]) : "r"(addr));
}
__device__ __forceinline__ void mma16816(float* d, const uint32_t* a,
                                         uint32_t b0, uint32_t b1) {
    asm volatile("mma.sync.aligned.m16n8k16.row.col.f32.f16.f16.f32 "
        "{%0,%1,%2,%3}, {%4,%5,%6,%7}, {%8,%9}, {%0,%1,%2,%3};"
        : "+f"(d[0]), "+f"(d[1]), "+f"(d[2]), "+f"(d[3])
        : "r"(a[0]), "r"(a[1]), "r"(a[2]), "r"(a[3]), "r"(b0), "r"(b1));
}

__global__ __launch_bounds__(256, 2) void k_hgemm(
    int mreal, int nreal, int kd,
    const __half* __restrict__ Ap, const __half* __restrict__ Bp,
    float* __restrict__ C, int ldc, int zeroDiag)
{
    extern __shared__ __half sh[];
    const int tid = threadIdx.x;
    const int wid = tid >> 5, lane = tid & 31;
    const int bm = blockIdx.y * BM, bn = blockIdx.x * BN;
    const int wm0 = (wid & 3) * 32, wn0 = (wid >> 2) * 64;
    const int nch = kd / BK;

    const __half* Ag = Ap + (size_t)bm * kd;
    const __half* Bg = Bp + (size_t)bn * kd;

    const int lc8 = tid & 7;          // 16B column within 64-half chunk
    const int lr0 = tid >> 3;         // base row

    float acc[2][8][4];
    #pragma unroll
    for (int mt = 0; mt < 2; mt++)
        #pragma unroll
        for (int n8 = 0; n8 < 8; n8++)
            #pragma unroll
            for (int q = 0; q < 4; q++) acc[mt][n8][q] = 0.f;

    // prologue: stages 0..STG-2
    #pragma unroll
    for (int s = 0; s < STG - 1; s++) {
        __half* sA = sh + s * STAGE_HALVES;
        __half* sB = sA + 128 * LDS_H;
        const __half* Asrc = Ag + s * BK;
        const __half* Bsrc = Bg + s * BK;
        #pragma unroll
        for (int i = 0; i < 4; i++) {
            int row = lr0 + i * 32;
            cpa16(smem_u32(&sA[row * LDS_H + lc8 * 8]), Asrc + (size_t)row * kd + lc8 * 8);
            cpa16(smem_u32(&sB[row * LDS_H + lc8 * 8]), Bsrc + (size_t)row * kd + lc8 * 8);
        }
        CP_COMMIT();
    }

    for (int c = 0; c < nch; c++) {
        CP_WAIT(STG - 2);
        __syncthreads();

        // prefetch chunk c+STG-1
        {
            int cf = c + STG - 1;
            if (cf < nch) {
                int s = cf % STG;
                __half* sA = sh + s * STAGE_HALVES;
                __half* sB = sA + 128 * LDS_H;
                const __half* Asrc = Ag + cf * BK;
                const __half* Bsrc = Bg + cf * BK;
                #pragma unroll
                for (int i = 0; i < 4; i++) {
                    int row = lr0 + i * 32;
                    cpa16(smem_u32(&sA[row * LDS_H + lc8 * 8]),
                          Asrc + (size_t)row * kd + lc8 * 8);
                    cpa16(smem_u32(&sB[row * LDS_H + lc8 * 8]),
                          Bsrc + (size_t)row * kd + lc8 * 8);
                }
            }
            CP_COMMIT();
        }

        // compute on stage c % STG
        {
            int s = c % STG;
            const __half* sA = sh + s * STAGE_HALVES;
            const __half* sB = sA + 128 * LDS_H;
            int ar = wm0 + (lane & 15);
            int ac = (lane >> 4) * 8;
            int br = wn0 + (lane & 7) + ((lane >> 4) & 1) * 8;
            int bc = ((lane >> 3) & 1) * 8;
            #pragma unroll
            for (int k16 = 0; k16 < 4; k16++) {
                uint32_t a[2][4];
                #pragma unroll
                for (int mt = 0; mt < 2; mt++)
                    ldm_x4(a[mt], smem_u32(&sA[(ar + mt * 16) * LDS_H + k16 * 16 + ac]));
                uint32_t b[4][4];
                #pragma unroll
                for (int ng = 0; ng < 4; ng++)
                    ldm_x4(b[ng], smem_u32(&sB[(br + ng * 16) * LDS_H + k16 * 16 + bc]));
                #pragma unroll
                for (int mt = 0; mt < 2; mt++)
                    #pragma unroll
                    for (int n8 = 0; n8 < 8; n8++) {
                        int ng = n8 >> 1, hi = (n8 & 1) << 1;
                        mma16816(acc[mt][n8], a[mt], b[ng][hi], b[ng][hi + 1]);
                    }
            }
        }
        __syncthreads();
    }

    // epilogue: direct coalesced stores (8x8 patches -> 8 full 32B sectors)
    int g = lane >> 2, tg = lane & 3;
    #pragma unroll
    for (int mt = 0; mt < 2; mt++) {
        #pragma unroll
        for (int n8 = 0; n8 < 8; n8++) {
            int r1 = bm + wm0 + mt * 16 + g;
            int r2 = r1 + 8;
            int c0 = bn + wn0 + n8 * 8 + tg * 2;
            float* a4 = acc[mt][n8];
            if (r1 < mreal) {
                if (c0 < nreal)
                    C[(size_t)r1 * ldc + c0] = (zeroDiag && r1 == c0) ? 0.f : a4[0];
                if (c0 + 1 < nreal)
                    C[(size_t)r1 * ldc + c0 + 1] = (zeroDiag && r1 == c0 + 1) ? 0.f : a4[1];
            }
            if (r2 < mreal) {
                if (c0 < nreal)
                    C[(size_t)r2 * ldc + c0] = (zeroDiag && r2 == c0) ? 0.f : a4[2];
                if (c0 + 1 < nreal)
                    C[(size_t)r2 * ldc + c0 + 1] = (zeroDiag && r2 == c0 + 1) ? 0.f : a4[3];
            }
        }
    }
}

// ---------------- unpool: res[perm[r]] += xup[r] ----------------
__global__ void k_unpool(float* __restrict__ res, const float* __restrict__ xup,
                         const int* __restrict__ perm, int k) {
    int idx = blockIdx.x * blockDim.x + threadIdx.x;
    if (idx >= k * CH) return;
    int r = idx / CH, j = idx % CH;
    res[(size_t)perm[r] * CH + j] += xup[idx];
}

// ---------------- host orchestration ----------------
struct DevPtrs {
    float *A0, *A1, *A2, *A3;
    __half *Ah, *Bh;
    float *x0, *x1, *x2, *x3, *xp, *y, *z, *part, *dpart, *score, *sval;
    float *dis[4], *slw[4];
    int *perm0, *perm1, *perm2, *rnk;
};
static DevPtrs P;
static bool g_init = false;

static void prep_deg(const float* A, int n, int lvl) {
    dim3 cs(cdiv(n, 256), DSPLIT);
    k_colsum<<<cs, 256>>>(A, n, P.dpart);
    k_degfin<<<cdiv(n, 256), 256>>>(A, n, P.dpart, P.dis[lvl], P.slw[lvl]);
}

template<int CIN, int COUT>
static void gcn(const float* A, int n, int lvl, const float* xin, const float* W,
                const float* b, bool relu, float* out) {
    k_xw<CIN, COUT><<<cdiv(n * COUT, 256), 256>>>(xin, n, W, P.dis[lvl], P.y, P.z);
    dim3 ag(cdiv(n, 256), RSPLIT);
    k_atzp<COUT><<<ag, 256>>>(A, n, P.z, P.part);
    k_fin<COUT><<<cdiv(n * COUT, 256), 256>>>(n, P.part, P.y, P.dis[lvl], P.slw[lvl],
                                              b, relu ? 1 : 0, out);
}

static void pool_level(const float* A, int n, int k, int kp, int kd,
                       const float* x, const float* p, int* perm, float* Anext) {
    k_score<<<cdiv(n, 256), 256>>>(x, n, p, P.score);
    k_rank2<<<cdiv(n, 256), 256>>>(P.score, n, k, perm, P.sval, P.rnk, x, P.xp);
    // A operand: row gather (coalesced)
    size_t tot = (size_t)kp * kd;
    k_gA<<<(int)((tot + 255) / 256), 256>>>(A, n, perm, k, kd, P.Ah);
    // B operand: tiled transpose-gather (coalesced), grid.y spans kd for padding
    dim3 tg(cdiv(n, 32), cdiv(kd, 32));
    k_gBt<<<tg, dim3(32, 8)>>>(A, n, P.rnk, kd, P.Bh);
    dim3 gg(kp / 128, kp / 128);
    k_hgemm<<<gg, 256, SMEM_HGEMM>>>(k, k, kd, P.Ah, P.Bh, Anext, k, 1);
}

extern "C" void kernel_launch(void* const* d_in, const int* in_sizes, int n_in,
                              void* d_out, int out_size) {
    if (!g_init) {
        cudaGetSymbolAddress((void**)&P.A0, g_A0);
        cudaGetSymbolAddress((void**)&P.A1, g_A1);
        cudaGetSymbolAddress((void**)&P.A2, g_A2);
        cudaGetSymbolAddress((void**)&P.A3, g_A3);
        cudaGetSymbolAddress((void**)&P.Ah, g_Ah);
        cudaGetSymbolAddress((void**)&P.Bh, g_Bh);
        cudaGetSymbolAddress((void**)&P.x0, g_x0);
        cudaGetSymbolAddress((void**)&P.x1, g_x1);
        cudaGetSymbolAddress((void**)&P.x2, g_x2);
        cudaGetSymbolAddress((void**)&P.x3, g_x3);
        cudaGetSymbolAddress((void**)&P.xp, g_xp);
        cudaGetSymbolAddress((void**)&P.y,  g_y);
        cudaGetSymbolAddress((void**)&P.z,  g_z);
        cudaGetSymbolAddress((void**)&P.part,  g_part);
        cudaGetSymbolAddress((void**)&P.dpart, g_dpart);
        float* disBase; float* slwBase;
        cudaGetSymbolAddress((void**)&disBase, g_disA);
        cudaGetSymbolAddress((void**)&slwBase, g_slwA);
        for (int l = 0; l < 4; l++) { P.dis[l] = disBase + l * N0; P.slw[l] = slwBase + l * N0; }
        cudaGetSymbolAddress((void**)&P.score, g_score);
        cudaGetSymbolAddress((void**)&P.sval,  g_sval);
        cudaGetSymbolAddress((void**)&P.perm0, g_perm0);
        cudaGetSymbolAddress((void**)&P.perm1, g_perm1);
        cudaGetSymbolAddress((void**)&P.perm2, g_perm2);
        cudaGetSymbolAddress((void**)&P.rnk,   g_rnk);
        cudaFuncSetAttribute(k_hgemm, cudaFuncAttributeMaxDynamicSharedMemorySize,
                             SMEM_HGEMM);
        g_init = true;
    }

    const float* x_in = (const float*)d_in[0];
    const int*   ei   = (const int*)d_in[1];
    const float* W0 = (const float*)d_in[2];  const float* b0 = (const float*)d_in[3];
    const float* W1 = (const float*)d_in[4];  const float* b1 = (const float*)d_in[5];
    const float* W2 = (const float*)d_in[6];  const float* b2 = (const float*)d_in[7];
    const float* W3 = (const float*)d_in[8];  const float* b3 = (const float*)d_in[9];
    const float* p1 = (const float*)d_in[10];
    const float* p2 = (const float*)d_in[11];
    const float* p3 = (const float*)d_in[12];
    const float* U0 = (const float*)d_in[13]; const float* c0 = (const float*)d_in[14];
    const float* U1 = (const float*)d_in[15]; const float* c1 = (const float*)d_in[16];
    const float* U2 = (const float*)d_in[17]; const float* c2 = (const float*)d_in[18];
    float* out = (float*)d_out;

    // A0 = dense adjacency with parallel-edge accumulation + unit self loops
    k_zero<<<cdiv(N0 * N0, 256), 256>>>(P.A0, N0 * N0);
    k_edges<<<cdiv(EDG, 256), 256>>>(ei, ei + EDG, P.A0);
    k_diag1<<<cdiv(N0, 256), 256>>>(P.A0);

    // ---- down path ----
    prep_deg(P.A0, N0, 0);
    gcn<20, 64>(P.A0, N0, 0, x_in, W0, b0, true, P.x0);

    pool_level(P.A0, N0, K1, KP1, KD1, P.x0, p1, P.perm0, P.A1);
    prep_deg(P.A1, K1, 1);
    gcn<64, 64>(P.A1, K1, 1, P.xp, W1, b1, true, P.x1);

    pool_level(P.A1, K1, K2, KP2, KD2, P.x1, p2, P.perm1, P.A2);
    prep_deg(P.A2, K2, 2);
    gcn<64, 64>(P.A2, K2, 2, P.xp, W2, b2, true, P.x2);

    pool_level(P.A2, K2, K3, KP3, KD3, P.x2, p3, P.perm2, P.A3);
    prep_deg(P.A3, K3, 3);
    gcn<64, 64>(P.A3, K3, 3, P.xp, W3, b3, true, P.x3);

    // ---- up path (degrees reused from down path) ----
    k_unpool<<<cdiv(K3 * CH, 256), 256>>>(P.x2, P.x3, P.perm2, K3);
    gcn<64, 64>(P.A2, K2, 2, P.x2, U0, c0, true, P.xp);

    k_unpool<<<cdiv(K2 * CH, 256), 256>>>(P.x1, P.xp, P.perm1, K2);
    gcn<64, 64>(P.A1, K1, 1, P.x1, U1, c1, true, P.xp);

    k_unpool<<<cdiv(K1 * CH, 256), 256>>>(P.x0, P.xp, P.perm0, K1);
    gcn<64, 20>(P.A0, N0, 0, P.x0, U2, c2, false, out);
}

// round 14
// speedup vs baseline: 1.1567x; 1.1489x over previous
#include <cuda_runtime.h>
#include <cuda_fp16.h>
#include <math.h>
#include <stdint.h>

// ---------------- problem constants ----------------
#define N0   4096
#define EDG  131072
#define K1   3277      // ceil(0.8*4096)
#define K2   2622      // ceil(0.8*3277)
#define K3   2098      // ceil(0.8*2622)
#define KP1  3328      // K1 padded to 128 (GEMM M/N tiles)
#define KP2  2688
#define KP3  2176
#define KD1  4096      // GEMM K dim padded to 64
#define KD2  3328
#define KD3  2624
#define CH   64
#define DSPLIT 32
#define RSPLIT 16
#define CAP  256       // max nnz per A0 row (Poisson(32); P(>100) ~ 1e-20)

// ---------------- device scratch (no allocation allowed) ----------------
__device__ float g_A0[(size_t)N0*N0];
__device__ float g_A1[(size_t)K1*K1];
__device__ float g_A2[(size_t)K2*K2];
__device__ float g_A3[(size_t)K3*K3];
__device__ __half g_Ah[(size_t)KP1*KD1];   // dense GEMM A operand; level1: Gt [kd][KP1]
__device__ __half g_Bh[(size_t)KP1*KD1];   // GEMM operand B, [N,K] row-major
__device__ float g_x0[N0*CH];
__device__ float g_x1[K1*CH];
__device__ float g_x2[K2*CH];
__device__ float g_x3[K3*CH];
__device__ float g_xp[N0*CH];
__device__ float g_y [N0*CH];
__device__ float g_z [N0*CH];
__device__ float g_part [(size_t)RSPLIT*N0*CH];
__device__ float g_dpart[(size_t)DSPLIT*N0];
__device__ float g_disA[4][N0];
__device__ float g_slwA[4][N0];
__device__ float g_score[N0];
__device__ float g_sval[N0];
__device__ int   g_perm0[K1];
__device__ int   g_perm1[K2];
__device__ int   g_perm2[K3];
__device__ int   g_rnk[N0];
__device__ int   g_nnzIdx[(size_t)K1*CAP];
__device__ float g_nnzVal[(size_t)K1*CAP];
__device__ int   g_nnzCnt[K1];

static inline int cdiv(int a, int b) { return (a + b - 1) / b; }

// ---------------- elementwise ----------------
__global__ void k_zero(float* p, int n) {
    int i = blockIdx.x * blockDim.x + threadIdx.x;
    if (i < n) p[i] = 0.f;
}

__global__ void k_edges(const int* __restrict__ src, const int* __restrict__ dst,
                        float* __restrict__ A) {
    int i = blockIdx.x * blockDim.x + threadIdx.x;
    if (i >= EDG) return;
    int s = src[i], d = dst[i];
    if (s != d) atomicAdd(&A[(size_t)s * N0 + d], 1.0f);   // exact integer adds
}

__global__ void k_diag1(float* A) {
    int i = blockIdx.x * blockDim.x + threadIdx.x;
    if (i < N0) A[(size_t)i * N0 + i] += 1.0f;
}

// ---------------- degree / normalization (computed ONCE per matrix) ----------------
__global__ void k_colsum(const float* __restrict__ A, int n, float* __restrict__ dpart) {
    int c = blockIdx.x * blockDim.x + threadIdx.x;
    if (c >= n) return;
    int chunk = (n + DSPLIT - 1) / DSPLIT;
    int r0 = blockIdx.y * chunk;
    int r1 = min(n, r0 + chunk);
    float s = 0.f;
    for (int r = r0; r < r1; r++) s += A[(size_t)r * n + c];
    dpart[(size_t)blockIdx.y * n + c] = s;
}

__global__ void k_degfin(const float* __restrict__ A, int n,
                         const float* __restrict__ dpart,
                         float* __restrict__ dis, float* __restrict__ slw) {
    int c = blockIdx.x * blockDim.x + threadIdx.x;
    if (c >= n) return;
    float s = 0.f;
    for (int q = 0; q < DSPLIT; q++) s += dpart[(size_t)q * n + c];
    float dg = A[(size_t)c * n + c];
    float sl = (dg == 0.f) ? 2.f : 0.f;    // add_remaining_self_loops, fill=2
    float deg = s + sl;
    slw[c] = sl;
    dis[c] = (deg > 0.f) ? rsqrtf(deg) : 0.f;
}

// ---------------- x @ W, scaled by dis ----------------
template<int CIN, int COUT>
__global__ void k_xw(const float* __restrict__ x, int n, const float* __restrict__ W,
                     const float* __restrict__ dis,
                     float* __restrict__ y, float* __restrict__ z) {
    int idx = blockIdx.x * blockDim.x + threadIdx.x;
    if (idx >= n * COUT) return;
    int r = idx / COUT, j = idx % COUT;
    float s = 0.f;
    #pragma unroll
    for (int k = 0; k < CIN; k++) s += x[(size_t)r * CIN + k] * W[k * COUT + j];
    y[idx] = s;
    z[idx] = dis[r] * s;
}

// ---------------- out_part = (A^T z) split over rows ----------------
template<int COUT>
__global__ void k_atzp(const float* __restrict__ A, int n,
                       const float* __restrict__ z, float* __restrict__ part) {
    const int RC = 8;
    __shared__ float zs[RC][COUT];
    int c = blockIdx.x * blockDim.x + threadIdx.x;
    int chunk = (n + RSPLIT - 1) / RSPLIT;
    int r0b = blockIdx.y * chunk;
    int r1  = min(n, r0b + chunk);
    float acc[COUT];
    #pragma unroll
    for (int j = 0; j < COUT; j++) acc[j] = 0.f;
    for (int r0 = r0b; r0 < r1; r0 += RC) {
        __syncthreads();
        for (int t = threadIdx.x; t < RC * COUT; t += blockDim.x) {
            int rr = t / COUT, j = t % COUT;
            int r = r0 + rr;
            zs[rr][j] = (r < r1) ? z[(size_t)r * COUT + j] : 0.f;
        }
        __syncthreads();
        int rmax = min(RC, r1 - r0);
        if (c < n) {
            for (int rr = 0; rr < rmax; rr++) {
                float a = A[(size_t)(r0 + rr) * n + c];
                #pragma unroll
                for (int j = 0; j < COUT; j++) acc[j] += a * zs[rr][j];
            }
        }
    }
    if (c < n) {
        #pragma unroll
        for (int j = 0; j < COUT; j++)
            part[((size_t)blockIdx.y * n + c) * COUT + j] = acc[j];
    }
}

template<int COUT>
__global__ void k_fin(int n, const float* __restrict__ part,
                      const float* __restrict__ y, const float* __restrict__ dis,
                      const float* __restrict__ slw, const float* __restrict__ b,
                      int doRelu, float* __restrict__ out) {
    int idx = blockIdx.x * blockDim.x + threadIdx.x;
    if (idx >= n * COUT) return;
    int c = idx / COUT, j = idx % COUT;
    float s = 0.f;
    for (int q = 0; q < RSPLIT; q++) s += part[((size_t)q * n + c) * COUT + j];
    float dc = dis[c];
    float v = dc * (s + slw[c] * dc * y[idx]) + b[j];
    if (doRelu) v = fmaxf(v, 0.f);
    out[idx] = v;
}

// ---------------- top-k pooling ----------------
__global__ void k_score(const float* __restrict__ x, int n,
                        const float* __restrict__ p, float* __restrict__ s) {
    int r = blockIdx.x * blockDim.x + threadIdx.x;
    if (r >= n) return;
    float pp = 0.f, dot = 0.f;
    #pragma unroll
    for (int k = 0; k < CH; k++) {
        float pk = p[k];
        pp += pk * pk;
        dot += x[(size_t)r * CH + k] * pk;
    }
    s[r] = tanhf(dot / sqrtf(pp));
}

// Fused: rank + perm + sval + inverse-perm + pooled features
// rank = #{j : s[j] > s[i]  ||  (s[j]==s[i] && j<i)}  -> matches lax.top_k order
__global__ void k_rank2(const float* __restrict__ score, int n, int k,
                        int* __restrict__ perm, float* __restrict__ sval,
                        int* __restrict__ rnk,
                        const float* __restrict__ x, float* __restrict__ xp) {
    __shared__ float ss[1024];
    int i = blockIdx.x * blockDim.x + threadIdx.x;
    float si = (i < n) ? score[i] : 0.f;
    int rank = 0;
    for (int j0 = 0; j0 < n; j0 += 1024) {
        int cnt = min(1024, n - j0);
        __syncthreads();
        for (int t = threadIdx.x; t < cnt; t += blockDim.x) ss[t] = score[j0 + t];
        __syncthreads();
        if (i < n) {
            for (int jj = 0; jj < cnt; jj++) {
                float sj = ss[jj];
                int j = j0 + jj;
                rank += (sj > si) || (sj == si && j < i);
            }
        }
    }
    if (i < n) {
        if (rank < k) {
            perm[rank] = i;
            sval[rank] = si;
            rnk[i] = rank;
            const float4* xr = (const float4*)(x + (size_t)i * CH);
            float4* xo = (float4*)(xp + (size_t)rank * CH);
            #pragma unroll
            for (int q = 0; q < CH / 4; q++) {
                float4 v = xr[q];
                v.x *= si; v.y *= si; v.z *= si; v.w *= si;
                xo[q] = v;
            }
        } else {
            rnk[i] = -1;
        }
    }
}

// ---------------- gathers -> fp16 GEMM operands ----------------
// A operand [kp x kd]: Aop[r][kk] = A1[perm[r], kk]   (A1 = unit diag, A off-diag)
__global__ void k_gA(const float* __restrict__ A, int n, const int* __restrict__ perm,
                     int k, int kd, __half* __restrict__ H) {
    size_t idx = (size_t)blockIdx.x * blockDim.x + threadIdx.x;
    int r = (int)(idx / kd), kk = (int)(idx % kd);
    float v = 0.f;
    if (r < k && kk < n) {
        int pr = perm[r];
        v = (kk == pr) ? 1.0f : A[(size_t)pr * n + kk];
    }
    H[idx] = __float2half(v);   // small integers: exact
}

// B operand [kpN x kd] via 32x32 tiled transpose-gather (coalesced both sides):
// Bop[rnk[j]][kk] = A1[kk][j]; grid.y spans kd so K-padding columns get zeros.
__global__ void k_gBt(const float* __restrict__ A, int n, const int* __restrict__ rnk,
                      int kd, __half* __restrict__ H) {
    __shared__ float t[32][33];
    int j0 = blockIdx.x * 32, k0 = blockIdx.y * 32;
    int tx = threadIdx.x, ty = threadIdx.y;   // 32 x 8
    #pragma unroll
    for (int i = 0; i < 32; i += 8) {
        int kk = k0 + ty + i, j = j0 + tx;
        float v = 0.f;
        if (kk < n && j < n) v = (kk == j) ? 1.0f : A[(size_t)kk * n + j];
        t[ty + i][tx] = v;
    }
    __syncthreads();
    #pragma unroll
    for (int i = 0; i < 32; i += 8) {
        int j = j0 + ty + i, kk = k0 + tx;
        if (j < n && kk < kd) {
            int r = rnk[j];
            if (r >= 0) H[(size_t)r * kd + kk] = __float2half(t[tx][ty + i]);
        }
    }
}

// ---------------- level-1 sparse path ----------------
// fp16 transpose: G[kk][c] = B[c][kk]  (B: [KP1 rows][kd cols], G: [kd rows][ldg cols])
__global__ void k_t16(const __half* __restrict__ B, int kd, int ldg,
                      __half* __restrict__ G) {
    __shared__ __half t[32][33];
    int c0 = blockIdx.x * 32, k0 = blockIdx.y * 32;
    int tx = threadIdx.x, ty = threadIdx.y;   // 32 x 8
    #pragma unroll
    for (int i = 0; i < 32; i += 8)
        t[ty + i][tx] = B[(size_t)(c0 + ty + i) * kd + (k0 + tx)];
    __syncthreads();
    #pragma unroll
    for (int i = 0; i < 32; i += 8)
        G[(size_t)(k0 + ty + i) * ldg + (c0 + tx)] = t[tx][ty + i];
}

// Extract nonzeros of selected A0 rows: one warp per output row r (row perm[r]).
// diag(A0)=1 always, so A1==A0 at level 1.
__global__ void k_extract(const float* __restrict__ A, int n,
                          const int* __restrict__ perm, int k,
                          int* __restrict__ nnzIdx, float* __restrict__ nnzVal,
                          int* __restrict__ nnzCnt) {
    int wid = threadIdx.x >> 5, lane = threadIdx.x & 31;
    int r = blockIdx.x * 8 + wid;
    if (r >= k) return;
    const float* row = A + (size_t)perm[r] * n;
    int cnt = 0;
    for (int j0 = 0; j0 < n; j0 += 32) {
        float v = row[j0 + lane];
        unsigned m = __ballot_sync(0xffffffffu, v != 0.f);
        if (v != 0.f) {
            int pos = cnt + __popc(m & ((1u << lane) - 1u));
            if (pos < CAP) {
                nnzIdx[(size_t)r * CAP + pos] = j0 + lane;
                nnzVal[(size_t)r * CAP + pos] = v;
            }
        }
        cnt += __popc(m);
    }
    if (lane == 0) nnzCnt[r] = min(cnt, CAP);
}

// SpMM: C[r][c] = sum_j val[j] * G[idx[j]][c], diag zeroed. One block per row.
__global__ __launch_bounds__(256) void k_spmm(
    const __half* __restrict__ G, int ldg,
    const int* __restrict__ nnzIdx, const float* __restrict__ nnzVal,
    const int* __restrict__ nnzCnt, int k,
    float* __restrict__ C, int ldc) {
    __shared__ int   sOff[CAP];
    __shared__ float sVal[CAP];
    int r = blockIdx.x;
    int cnt = nnzCnt[r];
    for (int t = threadIdx.x; t < cnt; t += 256) {
        sOff[t] = nnzIdx[(size_t)r * CAP + t] * ldg;
        sVal[t] = nnzVal[(size_t)r * CAP + t];
    }
    __syncthreads();
    for (int c0 = threadIdx.x * 2; c0 < k; c0 += 512) {
        float a0 = 0.f, a1 = 0.f;
        for (int j = 0; j < cnt; j++) {
            __half2 h = *(const __half2*)(G + sOff[j] + c0);
            float2 f = __half22float2(h);
            a0 += sVal[j] * f.x;
            a1 += sVal[j] * f.y;
        }
        C[(size_t)r * ldc + c0] = (c0 == r) ? 0.f : a0;
        if (c0 + 1 < k) C[(size_t)r * ldc + c0 + 1] = (c0 + 1 == r) ? 0.f : a1;
    }
}

// ---------------- mma.sync fp16 GEMM: C = A @ B^T, 128x128 tile ----------------
#define BM 128
#define BN 128
#define BK 64
#define STG 3
#define LDS_H 72                      // padded halves/row: 144B = 9 x 16B
#define STAGE_HALVES (2 * 128 * LDS_H)
#define SMEM_HGEMM (STG * STAGE_HALVES * 2)   // 110592 bytes -> 2 CTAs/SM

__device__ __forceinline__ uint32_t smem_u32(const void* p) {
    uint32_t a;
    asm("{ .reg .u64 t; cvta.to.shared.u64 t, %1; cvt.u32.u64 %0, t; }"
        : "=r"(a) : "l"(p));
    return a;
}
__device__ __forceinline__ void cpa16(uint32_t s, const void* g) {
    asm volatile("cp.async.cg.shared.global [%0], [%1], 16;" :: "r"(s), "l"(g));
}
#define CP_COMMIT() asm volatile("cp.async.commit_group;" ::: "memory")
#define CP_WAIT(n)  asm volatile("cp.async.wait_group %0;" :: "n"(n) : "memory")

__device__ __forceinline__ void ldm_x4(uint32_t* r, uint32_t addr) {
    asm volatile("ldmatrix.sync.aligned.m8n8.x4.shared.b16 {%0,%1,%2,%3}, [%4];"
        : "=r"(r[0]), "=r"(r[1]), "=r"(r[2]), "=r"(r[3]) : "r"(addr));
}
__device__ __forceinline__ void mma16816(float* d, const uint32_t* a,
                                         uint32_t b0, uint32_t b1) {
    asm volatile("mma.sync.aligned.m16n8k16.row.col.f32.f16.f16.f32 "
        "{%0,%1,%2,%3}, {%4,%5,%6,%7}, {%8,%9}, {%0,%1,%2,%3};"
        : "+f"(d[0]), "+f"(d[1]), "+f"(d[2]), "+f"(d[3])
        : "r"(a[0]), "r"(a[1]), "r"(a[2]), "r"(a[3]), "r"(b0), "r"(b1));
}

__global__ __launch_bounds__(256, 2) void k_hgemm(
    int mreal, int nreal, int kd,
    const __half* __restrict__ Ap, const __half* __restrict__ Bp,
    float* __restrict__ C, int ldc, int zeroDiag)
{
    extern __shared__ __half sh[];
    const int tid = threadIdx.x;
    const int wid = tid >> 5, lane = tid & 31;
    const int bm = blockIdx.y * BM, bn = blockIdx.x * BN;
    const int wm0 = (wid & 3) * 32, wn0 = (wid >> 2) * 64;
    const int nch = kd / BK;

    const __half* Ag = Ap + (size_t)bm * kd;
    const __half* Bg = Bp + (size_t)bn * kd;

    const int lc8 = tid & 7;          // 16B column within 64-half chunk
    const int lr0 = tid >> 3;         // base row

    float acc[2][8][4];
    #pragma unroll
    for (int mt = 0; mt < 2; mt++)
        #pragma unroll
        for (int n8 = 0; n8 < 8; n8++)
            #pragma unroll
            for (int q = 0; q < 4; q++) acc[mt][n8][q] = 0.f;

    // prologue: stages 0..STG-2
    #pragma unroll
    for (int s = 0; s < STG - 1; s++) {
        __half* sA = sh + s * STAGE_HALVES;
        __half* sB = sA + 128 * LDS_H;
        const __half* Asrc = Ag + s * BK;
        const __half* Bsrc = Bg + s * BK;
        #pragma unroll
        for (int i = 0; i < 4; i++) {
            int row = lr0 + i * 32;
            cpa16(smem_u32(&sA[row * LDS_H + lc8 * 8]), Asrc + (size_t)row * kd + lc8 * 8);
            cpa16(smem_u32(&sB[row * LDS_H + lc8 * 8]), Bsrc + (size_t)row * kd + lc8 * 8);
        }
        CP_COMMIT();
    }

    for (int c = 0; c < nch; c++) {
        CP_WAIT(STG - 2);
        __syncthreads();

        // prefetch chunk c+STG-1
        {
            int cf = c + STG - 1;
            if (cf < nch) {
                int s = cf % STG;
                __half* sA = sh + s * STAGE_HALVES;
                __half* sB = sA + 128 * LDS_H;
                const __half* Asrc = Ag + cf * BK;
                const __half* Bsrc = Bg + cf * BK;
                #pragma unroll
                for (int i = 0; i < 4; i++) {
                    int row = lr0 + i * 32;
                    cpa16(smem_u32(&sA[row * LDS_H + lc8 * 8]),
                          Asrc + (size_t)row * kd + lc8 * 8);
                    cpa16(smem_u32(&sB[row * LDS_H + lc8 * 8]),
                          Bsrc + (size_t)row * kd + lc8 * 8);
                }
            }
            CP_COMMIT();
        }

        // compute on stage c % STG
        {
            int s = c % STG;
            const __half* sA = sh + s * STAGE_HALVES;
            const __half* sB = sA + 128 * LDS_H;
            int ar = wm0 + (lane & 15);
            int ac = (lane >> 4) * 8;
            int br = wn0 + (lane & 7) + ((lane >> 4) & 1) * 8;
            int bc = ((lane >> 3) & 1) * 8;
            #pragma unroll
            for (int k16 = 0; k16 < 4; k16++) {
                uint32_t a[2][4];
                #pragma unroll
                for (int mt = 0; mt < 2; mt++)
                    ldm_x4(a[mt], smem_u32(&sA[(ar + mt * 16) * LDS_H + k16 * 16 + ac]));
                uint32_t b[4][4];
                #pragma unroll
                for (int ng = 0; ng < 4; ng++)
                    ldm_x4(b[ng], smem_u32(&sB[(br + ng * 16) * LDS_H + k16 * 16 + bc]));
                #pragma unroll
                for (int mt = 0; mt < 2; mt++)
                    #pragma unroll
                    for (int n8 = 0; n8 < 8; n8++) {
                        int ng = n8 >> 1, hi = (n8 & 1) << 1;
                        mma16816(acc[mt][n8], a[mt], b[ng][hi], b[ng][hi + 1]);
                    }
            }
        }
        __syncthreads();
    }

    // epilogue: direct coalesced stores (8x8 patches -> 8 full 32B sectors)
    int g = lane >> 2, tg = lane & 3;
    #pragma unroll
    for (int mt = 0; mt < 2; mt++) {
        #pragma unroll
        for (int n8 = 0; n8 < 8; n8++) {
            int r1 = bm + wm0 + mt * 16 + g;
            int r2 = r1 + 8;
            int c0 = bn + wn0 + n8 * 8 + tg * 2;
            float* a4 = acc[mt][n8];
            if (r1 < mreal) {
                if (c0 < nreal)
                    C[(size_t)r1 * ldc + c0] = (zeroDiag && r1 == c0) ? 0.f : a4[0];
                if (c0 + 1 < nreal)
                    C[(size_t)r1 * ldc + c0 + 1] = (zeroDiag && r1 == c0 + 1) ? 0.f : a4[1];
            }
            if (r2 < mreal) {
                if (c0 < nreal)
                    C[(size_t)r2 * ldc + c0] = (zeroDiag && r2 == c0) ? 0.f : a4[2];
                if (c0 + 1 < nreal)
                    C[(size_t)r2 * ldc + c0 + 1] = (zeroDiag && r2 == c0 + 1) ? 0.f : a4[3];
            }
        }
    }
}

// ---------------- unpool: res[perm[r]] += xup[r] ----------------
__global__ void k_unpool(float* __restrict__ res, const float* __restrict__ xup,
                         const int* __restrict__ perm, int k) {
    int idx = blockIdx.x * blockDim.x + threadIdx.x;
    if (idx >= k * CH) return;
    int r = idx / CH, j = idx % CH;
    res[(size_t)perm[r] * CH + j] += xup[idx];
}

// ---------------- host orchestration ----------------
struct DevPtrs {
    float *A0, *A1, *A2, *A3;
    __half *Ah, *Bh;
    float *x0, *x1, *x2, *x3, *xp, *y, *z, *part, *dpart, *score, *sval;
    float *dis[4], *slw[4];
    int *perm0, *perm1, *perm2, *rnk;
    int *nnzIdx; float *nnzVal; int *nnzCnt;
};
static DevPtrs P;
static bool g_init = false;

static void prep_deg(const float* A, int n, int lvl) {
    dim3 cs(cdiv(n, 256), DSPLIT);
    k_colsum<<<cs, 256>>>(A, n, P.dpart);
    k_degfin<<<cdiv(n, 256), 256>>>(A, n, P.dpart, P.dis[lvl], P.slw[lvl]);
}

template<int CIN, int COUT>
static void gcn(const float* A, int n, int lvl, const float* xin, const float* W,
                const float* b, bool relu, float* out) {
    k_xw<CIN, COUT><<<cdiv(n * COUT, 256), 256>>>(xin, n, W, P.dis[lvl], P.y, P.z);
    dim3 ag(cdiv(n, 256), RSPLIT);
    k_atzp<COUT><<<ag, 256>>>(A, n, P.z, P.part);
    k_fin<COUT><<<cdiv(n * COUT, 256), 256>>>(n, P.part, P.y, P.dis[lvl], P.slw[lvl],
                                              b, relu ? 1 : 0, out);
}

static void pool_level(const float* A, int n, int k, int kp, int kd,
                       const float* x, const float* p, int* perm, float* Anext,
                       bool sparse) {
    k_score<<<cdiv(n, 256), 256>>>(x, n, p, P.score);
    k_rank2<<<cdiv(n, 256), 256>>>(P.score, n, k, perm, P.sval, P.rnk, x, P.xp);
    // B operand: tiled transpose-gather (coalesced), grid.y spans kd for padding
    dim3 tg(cdiv(n, 32), cdiv(kd, 32));
    k_gBt<<<tg, dim3(32, 8)>>>(A, n, P.rnk, kd, P.Bh);
    if (sparse) {
        // Gt[kk][c] = Bh[c][kk] into g_Ah; then row-sparse SpMM
        dim3 tt(kp / 32, kd / 32);
        k_t16<<<tt, dim3(32, 8)>>>(P.Bh, kd, kp, P.Ah);
        k_extract<<<cdiv(k, 8), 256>>>(A, n, perm, k, P.nnzIdx, P.nnzVal, P.nnzCnt);
        k_spmm<<<k, 256>>>(P.Ah, kp, P.nnzIdx, P.nnzVal, P.nnzCnt, k, Anext, k);
    } else {
        size_t tot = (size_t)kp * kd;
        k_gA<<<(int)((tot + 255) / 256), 256>>>(A, n, perm, k, kd, P.Ah);
        dim3 gg(kp / 128, kp / 128);
        k_hgemm<<<gg, 256, SMEM_HGEMM>>>(k, k, kd, P.Ah, P.Bh, Anext, k, 1);
    }
}

extern "C" void kernel_launch(void* const* d_in, const int* in_sizes, int n_in,
                              void* d_out, int out_size) {
    if (!g_init) {
        cudaGetSymbolAddress((void**)&P.A0, g_A0);
        cudaGetSymbolAddress((void**)&P.A1, g_A1);
        cudaGetSymbolAddress((void**)&P.A2, g_A2);
        cudaGetSymbolAddress((void**)&P.A3, g_A3);
        cudaGetSymbolAddress((void**)&P.Ah, g_Ah);
        cudaGetSymbolAddress((void**)&P.Bh, g_Bh);
        cudaGetSymbolAddress((void**)&P.x0, g_x0);
        cudaGetSymbolAddress((void**)&P.x1, g_x1);
        cudaGetSymbolAddress((void**)&P.x2, g_x2);
        cudaGetSymbolAddress((void**)&P.x3, g_x3);
        cudaGetSymbolAddress((void**)&P.xp, g_xp);
        cudaGetSymbolAddress((void**)&P.y,  g_y);
        cudaGetSymbolAddress((void**)&P.z,  g_z);
        cudaGetSymbolAddress((void**)&P.part,  g_part);
        cudaGetSymbolAddress((void**)&P.dpart, g_dpart);
        float* disBase; float* slwBase;
        cudaGetSymbolAddress((void**)&disBase, g_disA);
        cudaGetSymbolAddress((void**)&slwBase, g_slwA);
        for (int l = 0; l < 4; l++) { P.dis[l] = disBase + l * N0; P.slw[l] = slwBase + l * N0; }
        cudaGetSymbolAddress((void**)&P.score, g_score);
        cudaGetSymbolAddress((void**)&P.sval,  g_sval);
        cudaGetSymbolAddress((void**)&P.perm0, g_perm0);
        cudaGetSymbolAddress((void**)&P.perm1, g_perm1);
        cudaGetSymbolAddress((void**)&P.perm2, g_perm2);
        cudaGetSymbolAddress((void**)&P.rnk,   g_rnk);
        cudaGetSymbolAddress((void**)&P.nnzIdx, g_nnzIdx);
        cudaGetSymbolAddress((void**)&P.nnzVal, g_nnzVal);
        cudaGetSymbolAddress((void**)&P.nnzCnt, g_nnzCnt);
        cudaFuncSetAttribute(k_hgemm, cudaFuncAttributeMaxDynamicSharedMemorySize,
                             SMEM_HGEMM);
        g_init = true;
    }

    const float* x_in = (const float*)d_in[0];
    const int*   ei   = (const int*)d_in[1];
    const float* W0 = (const float*)d_in[2];  const float* b0 = (const float*)d_in[3];
    const float* W1 = (const float*)d_in[4];  const float* b1 = (const float*)d_in[5];
    const float* W2 = (const float*)d_in[6];  const float* b2 = (const float*)d_in[7];
    const float* W3 = (const float*)d_in[8];  const float* b3 = (const float*)d_in[9];
    const float* p1 = (const float*)d_in[10];
    const float* p2 = (const float*)d_in[11];
    const float* p3 = (const float*)d_in[12];
    const float* U0 = (const float*)d_in[13]; const float* c0 = (const float*)d_in[14];
    const float* U1 = (const float*)d_in[15]; const float* c1 = (const float*)d_in[16];
    const float* U2 = (const float*)d_in[17]; const float* c2 = (const float*)d_in[18];
    float* out = (float*)d_out;

    // A0 = dense adjacency with parallel-edge accumulation + unit self loops
    k_zero<<<cdiv(N0 * N0, 256), 256>>>(P.A0, N0 * N0);
    k_edges<<<cdiv(EDG, 256), 256>>>(ei, ei + EDG, P.A0);
    k_diag1<<<cdiv(N0, 256), 256>>>(P.A0);

    // ---- down path ----
    prep_deg(P.A0, N0, 0);
    gcn<20, 64>(P.A0, N0, 0, x_in, W0, b0, true, P.x0);

    // level 1: A0 is ~0.8% dense -> sparse augment product
    pool_level(P.A0, N0, K1, KP1, KD1, P.x0, p1, P.perm0, P.A1, true);
    prep_deg(P.A1, K1, 1);
    gcn<64, 64>(P.A1, K1, 1, P.xp, W1, b1, true, P.x1);

    pool_level(P.A1, K1, K2, KP2, KD2, P.x1, p2, P.perm1, P.A2, false);
    prep_deg(P.A2, K2, 2);
    gcn<64, 64>(P.A2, K2, 2, P.xp, W2, b2, true, P.x2);

    pool_level(P.A2, K2, K3, KP3, KD3, P.x2, p3, P.perm2, P.A3, false);
    prep_deg(P.A3, K3, 3);
    gcn<64, 64>(P.A3, K3, 3, P.xp, W3, b3, true, P.x3);

    // ---- up path (degrees reused from down path) ----
    k_unpool<<<cdiv(K3 * CH, 256), 256>>>(P.x2, P.x3, P.perm2, K3);
    gcn<64, 64>(P.A2, K2, 2, P.x2, U0, c0, true, P.xp);

    k_unpool<<<cdiv(K2 * CH, 256), 256>>>(P.x1, P.xp, P.perm1, K2);
    gcn<64, 64>(P.A1, K1, 1, P.x1, U1, c1, true, P.xp);

    k_unpool<<<cdiv(K1 * CH, 256), 256>>>(P.x0, P.xp, P.perm0, K1);
    gcn<64, 20>(P.A0, N0, 0, P.x0, U2, c2, false, out);
}

// round 15
// speedup vs baseline: 1.2417x; 1.0735x over previous
#include <cuda_runtime.h>
#include <cuda_fp16.h>
#include <math.h>
#include <stdint.h>

// ---------------- problem constants ----------------
#define N0   4096
#define EDG  131072
#define K1   3277      // ceil(0.8*4096)
#define K2   2622      // ceil(0.8*3277)
#define K3   2098      // ceil(0.8*2622)
#define KP1  3328      // K1 padded to 128 (GEMM M/N tiles)
#define KP2  2688
#define KP3  2176
#define KD1  4096      // GEMM K dim padded to 64
#define KD2  3328
#define KD3  2624
#define CH   64
#define DSPLIT 32
#define RSPLIT 16
#define CAP  256       // max nnz per A0 row (Poisson(32); P(>255) ~ 0)

// ---------------- device scratch (no allocation allowed) ----------------
__device__ float g_A0[(size_t)N0*N0];
__device__ float g_A1[(size_t)K1*K1];
__device__ float g_A2[(size_t)K2*K2];
__device__ float g_A3[(size_t)K3*K3];
__device__ __half g_Ah[(size_t)KP1*KD1];   // dense GEMM A operand
__device__ __half g_Bh[(size_t)KP1*KD1];   // GEMM operand B, [N,K] row-major
__device__ float g_x0[N0*CH];
__device__ float g_x1[K1*CH];
__device__ float g_x2[K2*CH];
__device__ float g_x3[K3*CH];
__device__ float g_xp[N0*CH];
__device__ float g_y [N0*CH];
__device__ float g_z [N0*CH];
__device__ float g_part [(size_t)RSPLIT*N0*CH];
__device__ float g_dpart[(size_t)DSPLIT*N0];
__device__ float g_disA[4][N0];
__device__ float g_slwA[4][N0];
__device__ float g_score[N0];
__device__ float g_sval[N0];
__device__ int   g_perm0[K1];
__device__ int   g_perm1[K2];
__device__ int   g_perm2[K3];
__device__ int   g_rnk[N0];
__device__ int   g_nnzIdx[(size_t)N0*CAP];   // CSR of ALL A0 rows
__device__ float g_nnzVal[(size_t)N0*CAP];
__device__ int   g_nnzCnt[N0];

static inline int cdiv(int a, int b) { return (a + b - 1) / b; }

// ---------------- elementwise ----------------
__global__ void k_zero(float* p, int n) {
    int i = blockIdx.x * blockDim.x + threadIdx.x;
    if (i < n) p[i] = 0.f;
}

__global__ void k_edges(const int* __restrict__ src, const int* __restrict__ dst,
                        float* __restrict__ A) {
    int i = blockIdx.x * blockDim.x + threadIdx.x;
    if (i >= EDG) return;
    int s = src[i], d = dst[i];
    if (s != d) atomicAdd(&A[(size_t)s * N0 + d], 1.0f);   // exact integer adds
}

__global__ void k_diag1(float* A) {
    int i = blockIdx.x * blockDim.x + threadIdx.x;
    if (i < N0) A[(size_t)i * N0 + i] += 1.0f;
}

// ---------------- degree / normalization (computed ONCE per matrix) ----------------
__global__ void k_colsum(const float* __restrict__ A, int n, float* __restrict__ dpart) {
    int c = blockIdx.x * blockDim.x + threadIdx.x;
    if (c >= n) return;
    int chunk = (n + DSPLIT - 1) / DSPLIT;
    int r0 = blockIdx.y * chunk;
    int r1 = min(n, r0 + chunk);
    float s = 0.f;
    for (int r = r0; r < r1; r++) s += A[(size_t)r * n + c];
    dpart[(size_t)blockIdx.y * n + c] = s;
}

__global__ void k_degfin(const float* __restrict__ A, int n,
                         const float* __restrict__ dpart,
                         float* __restrict__ dis, float* __restrict__ slw) {
    int c = blockIdx.x * blockDim.x + threadIdx.x;
    if (c >= n) return;
    float s = 0.f;
    for (int q = 0; q < DSPLIT; q++) s += dpart[(size_t)q * n + c];
    float dg = A[(size_t)c * n + c];
    float sl = (dg == 0.f) ? 2.f : 0.f;    // add_remaining_self_loops, fill=2
    float deg = s + sl;
    slw[c] = sl;
    dis[c] = (deg > 0.f) ? rsqrtf(deg) : 0.f;
}

// ---------------- x @ W, scaled by dis ----------------
template<int CIN, int COUT>
__global__ void k_xw(const float* __restrict__ x, int n, const float* __restrict__ W,
                     const float* __restrict__ dis,
                     float* __restrict__ y, float* __restrict__ z) {
    int idx = blockIdx.x * blockDim.x + threadIdx.x;
    if (idx >= n * COUT) return;
    int r = idx / COUT, j = idx % COUT;
    float s = 0.f;
    #pragma unroll
    for (int k = 0; k < CIN; k++) s += x[(size_t)r * CIN + k] * W[k * COUT + j];
    y[idx] = s;
    z[idx] = dis[r] * s;
}

// ---------------- out_part = (A^T z) split over rows ----------------
template<int COUT>
__global__ void k_atzp(const float* __restrict__ A, int n,
                       const float* __restrict__ z, float* __restrict__ part) {
    const int RC = 8;
    __shared__ float zs[RC][COUT];
    int c = blockIdx.x * blockDim.x + threadIdx.x;
    int chunk = (n + RSPLIT - 1) / RSPLIT;
    int r0b = blockIdx.y * chunk;
    int r1  = min(n, r0b + chunk);
    float acc[COUT];
    #pragma unroll
    for (int j = 0; j < COUT; j++) acc[j] = 0.f;
    for (int r0 = r0b; r0 < r1; r0 += RC) {
        __syncthreads();
        for (int t = threadIdx.x; t < RC * COUT; t += blockDim.x) {
            int rr = t / COUT, j = t % COUT;
            int r = r0 + rr;
            zs[rr][j] = (r < r1) ? z[(size_t)r * COUT + j] : 0.f;
        }
        __syncthreads();
        int rmax = min(RC, r1 - r0);
        if (c < n) {
            for (int rr = 0; rr < rmax; rr++) {
                float a = A[(size_t)(r0 + rr) * n + c];
                #pragma unroll
                for (int j = 0; j < COUT; j++) acc[j] += a * zs[rr][j];
            }
        }
    }
    if (c < n) {
        #pragma unroll
        for (int j = 0; j < COUT; j++)
            part[((size_t)blockIdx.y * n + c) * COUT + j] = acc[j];
    }
}

template<int COUT>
__global__ void k_fin(int n, const float* __restrict__ part,
                      const float* __restrict__ y, const float* __restrict__ dis,
                      const float* __restrict__ slw, const float* __restrict__ b,
                      int doRelu, float* __restrict__ out) {
    int idx = blockIdx.x * blockDim.x + threadIdx.x;
    if (idx >= n * COUT) return;
    int c = idx / COUT, j = idx % COUT;
    float s = 0.f;
    for (int q = 0; q < RSPLIT; q++) s += part[((size_t)q * n + c) * COUT + j];
    float dc = dis[c];
    float v = dc * (s + slw[c] * dc * y[idx]) + b[j];
    if (doRelu) v = fmaxf(v, 0.f);
    out[idx] = v;
}

// ---------------- top-k pooling ----------------
__global__ void k_score(const float* __restrict__ x, int n,
                        const float* __restrict__ p, float* __restrict__ s) {
    int r = blockIdx.x * blockDim.x + threadIdx.x;
    if (r >= n) return;
    float pp = 0.f, dot = 0.f;
    #pragma unroll
    for (int k = 0; k < CH; k++) {
        float pk = p[k];
        pp += pk * pk;
        dot += x[(size_t)r * CH + k] * pk;
    }
    s[r] = tanhf(dot / sqrtf(pp));
}

// Fused: rank + perm + sval + inverse-perm + pooled features
// rank = #{j : s[j] > s[i]  ||  (s[j]==s[i] && j<i)}  -> matches lax.top_k order
__global__ void k_rank2(const float* __restrict__ score, int n, int k,
                        int* __restrict__ perm, float* __restrict__ sval,
                        int* __restrict__ rnk,
                        const float* __restrict__ x, float* __restrict__ xp) {
    __shared__ float ss[1024];
    int i = blockIdx.x * blockDim.x + threadIdx.x;
    float si = (i < n) ? score[i] : 0.f;
    int rank = 0;
    for (int j0 = 0; j0 < n; j0 += 1024) {
        int cnt = min(1024, n - j0);
        __syncthreads();
        for (int t = threadIdx.x; t < cnt; t += blockDim.x) ss[t] = score[j0 + t];
        __syncthreads();
        if (i < n) {
            for (int jj = 0; jj < cnt; jj++) {
                float sj = ss[jj];
                int j = j0 + jj;
                rank += (sj > si) || (sj == si && j < i);
            }
        }
    }
    if (i < n) {
        if (rank < k) {
            perm[rank] = i;
            sval[rank] = si;
            rnk[i] = rank;
            const float4* xr = (const float4*)(x + (size_t)i * CH);
            float4* xo = (float4*)(xp + (size_t)rank * CH);
            #pragma unroll
            for (int q = 0; q < CH / 4; q++) {
                float4 v = xr[q];
                v.x *= si; v.y *= si; v.z *= si; v.w *= si;
                xo[q] = v;
            }
        } else {
            rnk[i] = -1;
        }
    }
}

// ---------------- gathers -> fp16 GEMM operands ----------------
// A operand [kp x kd]: Aop[r][kk] = A1[perm[r], kk]   (A1 = unit diag, A off-diag)
__global__ void k_gA(const float* __restrict__ A, int n, const int* __restrict__ perm,
                     int k, int kd, __half* __restrict__ H) {
    size_t idx = (size_t)blockIdx.x * blockDim.x + threadIdx.x;
    int r = (int)(idx / kd), kk = (int)(idx % kd);
    float v = 0.f;
    if (r < k && kk < n) {
        int pr = perm[r];
        v = (kk == pr) ? 1.0f : A[(size_t)pr * n + kk];
    }
    H[idx] = __float2half(v);   // small integers: exact
}

// B operand [kpN x kd] via 32x32 tiled transpose-gather (coalesced both sides):
// Bop[rnk[j]][kk] = A1[kk][j]; grid.y spans kd so K-padding columns get zeros.
__global__ void k_gBt(const float* __restrict__ A, int n, const int* __restrict__ rnk,
                      int kd, __half* __restrict__ H) {
    __shared__ float t[32][33];
    int j0 = blockIdx.x * 32, k0 = blockIdx.y * 32;
    int tx = threadIdx.x, ty = threadIdx.y;   // 32 x 8
    #pragma unroll
    for (int i = 0; i < 32; i += 8) {
        int kk = k0 + ty + i, j = j0 + tx;
        float v = 0.f;
        if (kk < n && j < n) v = (kk == j) ? 1.0f : A[(size_t)kk * n + j];
        t[ty + i][tx] = v;
    }
    __syncthreads();
    #pragma unroll
    for (int i = 0; i < 32; i += 8) {
        int j = j0 + ty + i, kk = k0 + tx;
        if (j < n && kk < kd) {
            int r = rnk[j];
            if (r >= 0) H[(size_t)r * kd + kk] = __float2half(t[tx][ty + i]);
        }
    }
}

// ---------------- level-1 sparse path ----------------
// Extract nonzeros of ALL A0 rows: one warp per row. diag(A0)=1 so A1==A0.
__global__ void k_extract_all(const float* __restrict__ A, int n,
                              int* __restrict__ nnzIdx, float* __restrict__ nnzVal,
                              int* __restrict__ nnzCnt) {
    int wid = threadIdx.x >> 5, lane = threadIdx.x & 31;
    int r = blockIdx.x * 8 + wid;
    if (r >= n) return;
    const float* row = A + (size_t)r * n;
    int cnt = 0;
    for (int j0 = 0; j0 < n; j0 += 32) {
        float v = row[j0 + lane];
        unsigned m = __ballot_sync(0xffffffffu, v != 0.f);
        if (v != 0.f) {
            int pos = cnt + __popc(m & ((1u << lane) - 1u));
            if (pos < CAP) {
                nnzIdx[(size_t)r * CAP + pos] = j0 + lane;
                nnzVal[(size_t)r * CAP + pos] = v;
            }
        }
        cnt += __popc(m);
    }
    if (lane == 0) nnzCnt[r] = min(cnt, CAP);
}

// Sparse x sparse: C[r][c] = sum_kk A0[perm[r]][kk] * A0[kk][perm[c]], diag zeroed.
// One block per output row; scatter into shared accumulator via rnk.
__global__ __launch_bounds__(256) void k_spmm_ss(
    const int* __restrict__ nnzIdx, const float* __restrict__ nnzVal,
    const int* __restrict__ nnzCnt,
    const int* __restrict__ perm, const int* __restrict__ rnk, int k,
    float* __restrict__ C, int ldc) {
    __shared__ float accum[KP1];
    __shared__ int   rIdx[CAP];
    __shared__ float rVal[CAP];
    int r = blockIdx.x;
    int pr = perm[r];
    for (int t = threadIdx.x; t < KP1; t += 256) accum[t] = 0.f;
    int cnt = nnzCnt[pr];
    for (int t = threadIdx.x; t < cnt; t += 256) {
        rIdx[t] = nnzIdx[(size_t)pr * CAP + t];
        rVal[t] = nnzVal[(size_t)pr * CAP + t];
    }
    __syncthreads();
    int wid = threadIdx.x >> 5, lane = threadIdx.x & 31;
    for (int j = wid; j < cnt; j += 8) {
        int kk = rIdx[j];
        float v = rVal[j];
        int c2 = nnzCnt[kk];
        const int*   ci = nnzIdx + (size_t)kk * CAP;
        const float* cv = nnzVal + (size_t)kk * CAP;
        for (int l = lane; l < c2; l += 32) {
            int rc = rnk[ci[l]];
            if (rc >= 0) atomicAdd(&accum[rc], v * cv[l]);   // exact integer adds
        }
    }
    __syncthreads();
    for (int t = threadIdx.x; t < k; t += 256)
        C[(size_t)r * ldc + t] = (t == r) ? 0.f : accum[t];
}

// ---------------- mma.sync fp16 GEMM: C = A @ B^T, 128x128 tile ----------------
#define BM 128
#define BN 128
#define BK 64
#define STG 3
#define LDS_H 72                      // padded halves/row: 144B = 9 x 16B
#define STAGE_HALVES (2 * 128 * LDS_H)
#define SMEM_HGEMM (STG * STAGE_HALVES * 2)   // 110592 bytes -> 2 CTAs/SM

__device__ __forceinline__ uint32_t smem_u32(const void* p) {
    uint32_t a;
    asm("{ .reg .u64 t; cvta.to.shared.u64 t, %1; cvt.u32.u64 %0, t; }"
        : "=r"(a) : "l"(p));
    return a;
}
__device__ __forceinline__ void cpa16(uint32_t s, const void* g) {
    asm volatile("cp.async.cg.shared.global [%0], [%1], 16;" :: "r"(s), "l"(g));
}
#define CP_COMMIT() asm volatile("cp.async.commit_group;" ::: "memory")
#define CP_WAIT(n)  asm volatile("cp.async.wait_group %0;" :: "n"(n) : "memory")

__device__ __forceinline__ void ldm_x4(uint32_t* r, uint32_t addr) {
    asm volatile("ldmatrix.sync.aligned.m8n8.x4.shared.b16 {%0,%1,%2,%3}, [%4];"
        : "=r"(r[0]), "=r"(r[1]), "=r"(r[2]), "=r"(r[3]) : "r"(addr));
}
__device__ __forceinline__ void mma16816(float* d, const uint32_t* a,
                                         uint32_t b0, uint32_t b1) {
    asm volatile("mma.sync.aligned.m16n8k16.row.col.f32.f16.f16.f32 "
        "{%0,%1,%2,%3}, {%4,%5,%6,%7}, {%8,%9}, {%0,%1,%2,%3};"
        : "+f"(d[0]), "+f"(d[1]), "+f"(d[2]), "+f"(d[3])
        : "r"(a[0]), "r"(a[1]), "r"(a[2]), "r"(a[3]), "r"(b0), "r"(b1));
}

__global__ __launch_bounds__(256, 2) void k_hgemm(
    int mreal, int nreal, int kd,
    const __half* __restrict__ Ap, const __half* __restrict__ Bp,
    float* __restrict__ C, int ldc, int zeroDiag)
{
    extern __shared__ __half sh[];
    const int tid = threadIdx.x;
    const int wid = tid >> 5, lane = tid & 31;
    const int bm = blockIdx.y * BM, bn = blockIdx.x * BN;
    const int wm0 = (wid & 3) * 32, wn0 = (wid >> 2) * 64;
    const int nch = kd / BK;

    const __half* Ag = Ap + (size_t)bm * kd;
    const __half* Bg = Bp + (size_t)bn * kd;

    const int lc8 = tid & 7;          // 16B column within 64-half chunk
    const int lr0 = tid >> 3;         // base row

    float acc[2][8][4];
    #pragma unroll
    for (int mt = 0; mt < 2; mt++)
        #pragma unroll
        for (int n8 = 0; n8 < 8; n8++)
            #pragma unroll
            for (int q = 0; q < 4; q++) acc[mt][n8][q] = 0.f;

    // prologue: stages 0..STG-2
    #pragma unroll
    for (int s = 0; s < STG - 1; s++) {
        __half* sA = sh + s * STAGE_HALVES;
        __half* sB = sA + 128 * LDS_H;
        const __half* Asrc = Ag + s * BK;
        const __half* Bsrc = Bg + s * BK;
        #pragma unroll
        for (int i = 0; i < 4; i++) {
            int row = lr0 + i * 32;
            cpa16(smem_u32(&sA[row * LDS_H + lc8 * 8]), Asrc + (size_t)row * kd + lc8 * 8);
            cpa16(smem_u32(&sB[row * LDS_H + lc8 * 8]), Bsrc + (size_t)row * kd + lc8 * 8);
        }
        CP_COMMIT();
    }

    for (int c = 0; c < nch; c++) {
        CP_WAIT(STG - 2);
        __syncthreads();

        // prefetch chunk c+STG-1
        {
            int cf = c + STG - 1;
            if (cf < nch) {
                int s = cf % STG;
                __half* sA = sh + s * STAGE_HALVES;
                __half* sB = sA + 128 * LDS_H;
                const __half* Asrc = Ag + cf * BK;
                const __half* Bsrc = Bg + cf * BK;
                #pragma unroll
                for (int i = 0; i < 4; i++) {
                    int row = lr0 + i * 32;
                    cpa16(smem_u32(&sA[row * LDS_H + lc8 * 8]),
                          Asrc + (size_t)row * kd + lc8 * 8);
                    cpa16(smem_u32(&sB[row * LDS_H + lc8 * 8]),
                          Bsrc + (size_t)row * kd + lc8 * 8);
                }
            }
            CP_COMMIT();
        }

        // compute on stage c % STG
        {
            int s = c % STG;
            const __half* sA = sh + s * STAGE_HALVES;
            const __half* sB = sA + 128 * LDS_H;
            int ar = wm0 + (lane & 15);
            int ac = (lane >> 4) * 8;
            int br = wn0 + (lane & 7) + ((lane >> 4) & 1) * 8;
            int bc = ((lane >> 3) & 1) * 8;
            #pragma unroll
            for (int k16 = 0; k16 < 4; k16++) {
                uint32_t a[2][4];
                #pragma unroll
                for (int mt = 0; mt < 2; mt++)
                    ldm_x4(a[mt], smem_u32(&sA[(ar + mt * 16) * LDS_H + k16 * 16 + ac]));
                uint32_t b[4][4];
                #pragma unroll
                for (int ng = 0; ng < 4; ng++)
                    ldm_x4(b[ng], smem_u32(&sB[(br + ng * 16) * LDS_H + k16 * 16 + bc]));
                #pragma unroll
                for (int mt = 0; mt < 2; mt++)
                    #pragma unroll
                    for (int n8 = 0; n8 < 8; n8++) {
                        int ng = n8 >> 1, hi = (n8 & 1) << 1;
                        mma16816(acc[mt][n8], a[mt], b[ng][hi], b[ng][hi + 1]);
                    }
            }
        }
        __syncthreads();
    }

    // epilogue: direct coalesced stores (8x8 patches -> 8 full 32B sectors)
    int g = lane >> 2, tg = lane & 3;
    #pragma unroll
    for (int mt = 0; mt < 2; mt++) {
        #pragma unroll
        for (int n8 = 0; n8 < 8; n8++) {
            int r1 = bm + wm0 + mt * 16 + g;
            int r2 = r1 + 8;
            int c0 = bn + wn0 + n8 * 8 + tg * 2;
            float* a4 = acc[mt][n8];
            if (r1 < mreal) {
                if (c0 < nreal)
                    C[(size_t)r1 * ldc + c0] = (zeroDiag && r1 == c0) ? 0.f : a4[0];
                if (c0 + 1 < nreal)
                    C[(size_t)r1 * ldc + c0 + 1] = (zeroDiag && r1 == c0 + 1) ? 0.f : a4[1];
            }
            if (r2 < mreal) {
                if (c0 < nreal)
                    C[(size_t)r2 * ldc + c0] = (zeroDiag && r2 == c0) ? 0.f : a4[2];
                if (c0 + 1 < nreal)
                    C[(size_t)r2 * ldc + c0 + 1] = (zeroDiag && r2 == c0 + 1) ? 0.f : a4[3];
            }
        }
    }
}

// ---------------- unpool: res[perm[r]] += xup[r] ----------------
__global__ void k_unpool(float* __restrict__ res, const float* __restrict__ xup,
                         const int* __restrict__ perm, int k) {
    int idx = blockIdx.x * blockDim.x + threadIdx.x;
    if (idx >= k * CH) return;
    int r = idx / CH, j = idx % CH;
    res[(size_t)perm[r] * CH + j] += xup[idx];
}

// ---------------- host orchestration ----------------
struct DevPtrs {
    float *A0, *A1, *A2, *A3;
    __half *Ah, *Bh;
    float *x0, *x1, *x2, *x3, *xp, *y, *z, *part, *dpart, *score, *sval;
    float *dis[4], *slw[4];
    int *perm0, *perm1, *perm2, *rnk;
    int *nnzIdx; float *nnzVal; int *nnzCnt;
};
static DevPtrs P;
static bool g_init = false;

static void prep_deg(const float* A, int n, int lvl) {
    dim3 cs(cdiv(n, 256), DSPLIT);
    k_colsum<<<cs, 256>>>(A, n, P.dpart);
    k_degfin<<<cdiv(n, 256), 256>>>(A, n, P.dpart, P.dis[lvl], P.slw[lvl]);
}

template<int CIN, int COUT>
static void gcn(const float* A, int n, int lvl, const float* xin, const float* W,
                const float* b, bool relu, float* out) {
    k_xw<CIN, COUT><<<cdiv(n * COUT, 256), 256>>>(xin, n, W, P.dis[lvl], P.y, P.z);
    dim3 ag(cdiv(n, 256), RSPLIT);
    k_atzp<COUT><<<ag, 256>>>(A, n, P.z, P.part);
    k_fin<COUT><<<cdiv(n * COUT, 256), 256>>>(n, P.part, P.y, P.dis[lvl], P.slw[lvl],
                                              b, relu ? 1 : 0, out);
}

static void pool_level(const float* A, int n, int k, int kp, int kd,
                       const float* x, const float* p, int* perm, float* Anext,
                       bool sparse) {
    k_score<<<cdiv(n, 256), 256>>>(x, n, p, P.score);
    k_rank2<<<cdiv(n, 256), 256>>>(P.score, n, k, perm, P.sval, P.rnk, x, P.xp);
    if (sparse) {
        // CSR of all A0 rows, then sparse x sparse scatter product
        k_extract_all<<<cdiv(n, 8), 256>>>(A, n, P.nnzIdx, P.nnzVal, P.nnzCnt);
        k_spmm_ss<<<k, 256>>>(P.nnzIdx, P.nnzVal, P.nnzCnt, perm, P.rnk, k, Anext, k);
    } else {
        dim3 tg(cdiv(n, 32), cdiv(kd, 32));
        k_gBt<<<tg, dim3(32, 8)>>>(A, n, P.rnk, kd, P.Bh);
        size_t tot = (size_t)kp * kd;
        k_gA<<<(int)((tot + 255) / 256), 256>>>(A, n, perm, k, kd, P.Ah);
        dim3 gg(kp / 128, kp / 128);
        k_hgemm<<<gg, 256, SMEM_HGEMM>>>(k, k, kd, P.Ah, P.Bh, Anext, k, 1);
    }
}

extern "C" void kernel_launch(void* const* d_in, const int* in_sizes, int n_in,
                              void* d_out, int out_size) {
    if (!g_init) {
        cudaGetSymbolAddress((void**)&P.A0, g_A0);
        cudaGetSymbolAddress((void**)&P.A1, g_A1);
        cudaGetSymbolAddress((void**)&P.A2, g_A2);
        cudaGetSymbolAddress((void**)&P.A3, g_A3);
        cudaGetSymbolAddress((void**)&P.Ah, g_Ah);
        cudaGetSymbolAddress((void**)&P.Bh, g_Bh);
        cudaGetSymbolAddress((void**)&P.x0, g_x0);
        cudaGetSymbolAddress((void**)&P.x1, g_x1);
        cudaGetSymbolAddress((void**)&P.x2, g_x2);
        cudaGetSymbolAddress((void**)&P.x3, g_x3);
        cudaGetSymbolAddress((void**)&P.xp, g_xp);
        cudaGetSymbolAddress((void**)&P.y,  g_y);
        cudaGetSymbolAddress((void**)&P.z,  g_z);
        cudaGetSymbolAddress((void**)&P.part,  g_part);
        cudaGetSymbolAddress((void**)&P.dpart, g_dpart);
        float* disBase; float* slwBase;
        cudaGetSymbolAddress((void**)&disBase, g_disA);
        cudaGetSymbolAddress((void**)&slwBase, g_slwA);
        for (int l = 0; l < 4; l++) { P.dis[l] = disBase + l * N0; P.slw[l] = slwBase + l * N0; }
        cudaGetSymbolAddress((void**)&P.score, g_score);
        cudaGetSymbolAddress((void**)&P.sval,  g_sval);
        cudaGetSymbolAddress((void**)&P.perm0, g_perm0);
        cudaGetSymbolAddress((void**)&P.perm1, g_perm1);
        cudaGetSymbolAddress((void**)&P.perm2, g_perm2);
        cudaGetSymbolAddress((void**)&P.rnk,   g_rnk);
        cudaGetSymbolAddress((void**)&P.nnzIdx, g_nnzIdx);
        cudaGetSymbolAddress((void**)&P.nnzVal, g_nnzVal);
        cudaGetSymbolAddress((void**)&P.nnzCnt, g_nnzCnt);
        cudaFuncSetAttribute(k_hgemm, cudaFuncAttributeMaxDynamicSharedMemorySize,
                             SMEM_HGEMM);
        g_init = true;
    }

    const float* x_in = (const float*)d_in[0];
    const int*   ei   = (const int*)d_in[1];
    const float* W0 = (const float*)d_in[2];  const float* b0 = (const float*)d_in[3];
    const float* W1 = (const float*)d_in[4];  const float* b1 = (const float*)d_in[5];
    const float* W2 = (const float*)d_in[6];  const float* b2 = (const float*)d_in[7];
    const float* W3 = (const float*)d_in[8];  const float* b3 = (const float*)d_in[9];
    const float* p1 = (const float*)d_in[10];
    const float* p2 = (const float*)d_in[11];
    const float* p3 = (const float*)d_in[12];
    const float* U0 = (const float*)d_in[13]; const float* c0 = (const float*)d_in[14];
    const float* U1 = (const float*)d_in[15]; const float* c1 = (const float*)d_in[16];
    const float* U2 = (const float*)d_in[17]; const float* c2 = (const float*)d_in[18];
    float* out = (float*)d_out;

    // A0 = dense adjacency with parallel-edge accumulation + unit self loops
    k_zero<<<cdiv(N0 * N0, 256), 256>>>(P.A0, N0 * N0);
    k_edges<<<cdiv(EDG, 256), 256>>>(ei, ei + EDG, P.A0);
    k_diag1<<<cdiv(N0, 256), 256>>>(P.A0);

    // ---- down path ----
    prep_deg(P.A0, N0, 0);
    gcn<20, 64>(P.A0, N0, 0, x_in, W0, b0, true, P.x0);

    // level 1: A0 is ~0.8% dense -> sparse x sparse augment product
    pool_level(P.A0, N0, K1, KP1, KD1, P.x0, p1, P.perm0, P.A1, true);
    prep_deg(P.A1, K1, 1);
    gcn<64, 64>(P.A1, K1, 1, P.xp, W1, b1, true, P.x1);

    pool_level(P.A1, K1, K2, KP2, KD2, P.x1, p2, P.perm1, P.A2, false);
    prep_deg(P.A2, K2, 2);
    gcn<64, 64>(P.A2, K2, 2, P.xp, W2, b2, true, P.x2);

    pool_level(P.A2, K2, K3, KP3, KD3, P.x2, p3, P.perm2, P.A3, false);
    prep_deg(P.A3, K3, 3);
    gcn<64, 64>(P.A3, K3, 3, P.xp, W3, b3, true, P.x3);

    // ---- up path (degrees reused from down path) ----
    k_unpool<<<cdiv(K3 * CH, 256), 256>>>(P.x2, P.x3, P.perm2, K3);
    gcn<64, 64>(P.A2, K2, 2, P.x2, U0, c0, true, P.xp);

    k_unpool<<<cdiv(K2 * CH, 256), 256>>>(P.x1, P.xp, P.perm1, K2);
    gcn<64, 64>(P.A1, K1, 1, P.x1, U1, c1, true, P.xp);

    k_unpool<<<cdiv(K1 * CH, 256), 256>>>(P.x0, P.xp, P.perm0, K1);
    gcn<64, 20>(P.A0, N0, 0, P.x0, U2, c2, false, out);
}

// round 16
// speedup vs baseline: 1.2550x; 1.0108x over previous
#include <cuda_runtime.h>
#include <cuda_fp16.h>
#include <math.h>
#include <stdint.h>

// ---------------- problem constants ----------------
#define N0   4096
#define EDG  131072
#define K1   3277      // ceil(0.8*4096)
#define K2   2622      // ceil(0.8*3277)
#define K3   2098      // ceil(0.8*2622)
#define KP1  3328      // K1 padded to 128 (GEMM M/N tiles)
#define KP2  2688
#define KP3  2176
#define KD1  4096      // GEMM K dim padded to 64
#define KD2  3328
#define KD3  2624
#define CH   64
#define DSPLIT 32
#define RSPLIT 16
#define CAP  256       // max nnz per A0 row (Poisson(32); P(>255) ~ 0)

// ---------------- device scratch (no allocation allowed) ----------------
__device__ float g_A0[(size_t)N0*N0];
__device__ float g_A1[(size_t)K1*K1];
__device__ float g_A2[(size_t)K2*K2];
__device__ float g_A3[(size_t)K3*K3];
__device__ __half g_Ah[(size_t)KP1*KD1];   // dense GEMM A operand
__device__ __half g_Bh[(size_t)KP1*KD1];   // GEMM operand B, [N,K] row-major
__device__ float g_x0[N0*CH];
__device__ float g_x1[K1*CH];
__device__ float g_x2[K2*CH];
__device__ float g_x3[K3*CH];
__device__ float g_xp[N0*CH];
__device__ float g_y [N0*CH];
__device__ float g_z [N0*CH];
__device__ float g_part [(size_t)RSPLIT*N0*CH];
__device__ float g_dpart[(size_t)DSPLIT*N0];
__device__ float g_disA[4][N0];
__device__ float g_slwA[4][N0];
__device__ float g_score[N0];
__device__ float g_sval[N0];
__device__ int   g_perm0[K1];
__device__ int   g_perm1[K2];
__device__ int   g_perm2[K3];
__device__ int   g_rnk[N0];
__device__ int   g_nnzIdx[(size_t)N0*CAP];   // CSR of ALL A0 rows
__device__ float g_nnzVal[(size_t)N0*CAP];
__device__ int   g_nnzCnt[N0];

static inline int cdiv(int a, int b) { return (a + b - 1) / b; }

// ---------------- elementwise ----------------
__global__ void k_zero(float* p, int n) {
    int i = blockIdx.x * blockDim.x + threadIdx.x;
    if (i < n) p[i] = 0.f;
}

__global__ void k_edges(const int* __restrict__ src, const int* __restrict__ dst,
                        float* __restrict__ A) {
    int i = blockIdx.x * blockDim.x + threadIdx.x;
    if (i >= EDG) return;
    int s = src[i], d = dst[i];
    if (s != d) atomicAdd(&A[(size_t)s * N0 + d], 1.0f);   // exact integer adds
}

__global__ void k_diag1(float* A) {
    int i = blockIdx.x * blockDim.x + threadIdx.x;
    if (i < N0) A[(size_t)i * N0 + i] += 1.0f;
}

__global__ void k_zdiag(float* A, int n) {
    int i = blockIdx.x * blockDim.x + threadIdx.x;
    if (i < n) A[(size_t)i * n + i] = 0.f;
}

// ---------------- degree / normalization (computed ONCE per matrix) ----------------
__global__ void k_colsum(const float* __restrict__ A, int n, float* __restrict__ dpart) {
    int c = blockIdx.x * blockDim.x + threadIdx.x;
    if (c >= n) return;
    int chunk = (n + DSPLIT - 1) / DSPLIT;
    int r0 = blockIdx.y * chunk;
    int r1 = min(n, r0 + chunk);
    float s = 0.f;
    for (int r = r0; r < r1; r++) s += A[(size_t)r * n + c];
    dpart[(size_t)blockIdx.y * n + c] = s;
}

__global__ void k_degfin(const float* __restrict__ A, int n,
                         const float* __restrict__ dpart,
                         float* __restrict__ dis, float* __restrict__ slw) {
    int c = blockIdx.x * blockDim.x + threadIdx.x;
    if (c >= n) return;
    float s = 0.f;
    for (int q = 0; q < DSPLIT; q++) s += dpart[(size_t)q * n + c];
    float dg = A[(size_t)c * n + c];
    float sl = (dg == 0.f) ? 2.f : 0.f;    // add_remaining_self_loops, fill=2
    float deg = s + sl;
    slw[c] = sl;
    dis[c] = (deg > 0.f) ? rsqrtf(deg) : 0.f;
}

// ---------------- x @ W, scaled by dis ----------------
template<int CIN, int COUT>
__global__ void k_xw(const float* __restrict__ x, int n, const float* __restrict__ W,
                     const float* __restrict__ dis,
                     float* __restrict__ y, float* __restrict__ z) {
    int idx = blockIdx.x * blockDim.x + threadIdx.x;
    if (idx >= n * COUT) return;
    int r = idx / COUT, j = idx % COUT;
    float s = 0.f;
    #pragma unroll
    for (int k = 0; k < CIN; k++) s += x[(size_t)r * CIN + k] * W[k * COUT + j];
    y[idx] = s;
    z[idx] = dis[r] * s;
}

// ---------------- out_part = (A^T z) split over rows ----------------
template<int COUT>
__global__ void k_atzp(const float* __restrict__ A, int n,
                       const float* __restrict__ z, float* __restrict__ part) {
    const int RC = 8;
    __shared__ float zs[RC][COUT];
    int c = blockIdx.x * blockDim.x + threadIdx.x;
    int chunk = (n + RSPLIT - 1) / RSPLIT;
    int r0b = blockIdx.y * chunk;
    int r1  = min(n, r0b + chunk);
    float acc[COUT];
    #pragma unroll
    for (int j = 0; j < COUT; j++) acc[j] = 0.f;
    for (int r0 = r0b; r0 < r1; r0 += RC) {
        __syncthreads();
        for (int t = threadIdx.x; t < RC * COUT; t += blockDim.x) {
            int rr = t / COUT, j = t % COUT;
            int r = r0 + rr;
            zs[rr][j] = (r < r1) ? z[(size_t)r * COUT + j] : 0.f;
        }
        __syncthreads();
        int rmax = min(RC, r1 - r0);
        if (c < n) {
            for (int rr = 0; rr < rmax; rr++) {
                float a = A[(size_t)(r0 + rr) * n + c];
                #pragma unroll
                for (int j = 0; j < COUT; j++) acc[j] += a * zs[rr][j];
            }
        }
    }
    if (c < n) {
        #pragma unroll
        for (int j = 0; j < COUT; j++)
            part[((size_t)blockIdx.y * n + c) * COUT + j] = acc[j];
    }
}

// Finalize conv + optional fused unpool (resAdd) + optional fused score.
// Score dot/pp use ascending-k sequential order, bit-identical to the old k_score.
template<int COUT>
__global__ void k_fin(int n, const float* __restrict__ part,
                      const float* __restrict__ y, const float* __restrict__ dis,
                      const float* __restrict__ slw, const float* __restrict__ b,
                      int doRelu, float* __restrict__ out,
                      float* __restrict__ resAdd, const int* __restrict__ perm,
                      const float* __restrict__ p, float* __restrict__ score) {
    __shared__ float sp[COUT];
    __shared__ float sv[256];
    int idx = blockIdx.x * 256 + threadIdx.x;
    bool valid = idx < n * COUT;
    int c = idx / COUT, j = idx - c * COUT;
    if (p && threadIdx.x < COUT) sp[threadIdx.x] = p[threadIdx.x];
    float v = 0.f;
    if (valid) {
        float s = 0.f;
        for (int q = 0; q < RSPLIT; q++) s += part[((size_t)q * n + c) * COUT + j];
        float dc = dis[c];
        v = dc * (s + slw[c] * dc * y[idx]) + b[j];
        if (doRelu) v = fmaxf(v, 0.f);
        if (out) out[idx] = v;
        if (resAdd) resAdd[(size_t)perm[c] * COUT + j] += v;  // unique (c,j): race-free
    }
    if (p) {
        sv[threadIdx.x] = valid ? v : 0.f;
        __syncthreads();
        int w = threadIdx.x;
        if (w < 256 / COUT) {
            int row = blockIdx.x * (256 / COUT) + w;
            if (row < n) {
                float pp = 0.f, dot = 0.f;
                for (int k2 = 0; k2 < COUT; k2++) {
                    float pk = sp[k2];
                    pp  += pk * pk;
                    dot += sv[w * COUT + k2] * pk;
                }
                score[row] = tanhf(dot / sqrtf(pp));
            }
        }
    }
}

// Fused: rank + perm + sval + inverse-perm + pooled features
// rank = #{j : s[j] > s[i]  ||  (s[j]==s[i] && j<i)}  -> matches lax.top_k order
__global__ void k_rank2(const float* __restrict__ score, int n, int k,
                        int* __restrict__ perm, float* __restrict__ sval,
                        int* __restrict__ rnk,
                        const float* __restrict__ x, float* __restrict__ xp) {
    __shared__ float ss[1024];
    int i = blockIdx.x * blockDim.x + threadIdx.x;
    float si = (i < n) ? score[i] : 0.f;
    int rank = 0;
    for (int j0 = 0; j0 < n; j0 += 1024) {
        int cnt = min(1024, n - j0);
        __syncthreads();
        for (int t = threadIdx.x; t < cnt; t += blockDim.x) ss[t] = score[j0 + t];
        __syncthreads();
        if (i < n) {
            for (int jj = 0; jj < cnt; jj++) {
                float sj = ss[jj];
                int j = j0 + jj;
                rank += (sj > si) || (sj == si && j < i);
            }
        }
    }
    if (i < n) {
        if (rank < k) {
            perm[rank] = i;
            sval[rank] = si;
            rnk[i] = rank;
            const float4* xr = (const float4*)(x + (size_t)i * CH);
            float4* xo = (float4*)(xp + (size_t)rank * CH);
            #pragma unroll
            for (int q = 0; q < CH / 4; q++) {
                float4 v = xr[q];
                v.x *= si; v.y *= si; v.z *= si; v.w *= si;
                xo[q] = v;
            }
        } else {
            rnk[i] = -1;
        }
    }
}

// ---------------- gathers -> fp16 GEMM operands ----------------
// A operand [kp x kd]: Aop[r][kk] = A1[perm[r], kk]   (A1 = unit diag, A off-diag)
__global__ void k_gA(const float* __restrict__ A, int n, const int* __restrict__ perm,
                     int k, int kd, __half* __restrict__ H) {
    size_t idx = (size_t)blockIdx.x * blockDim.x + threadIdx.x;
    int r = (int)(idx / kd), kk = (int)(idx % kd);
    float v = 0.f;
    if (r < k && kk < n) {
        int pr = perm[r];
        v = (kk == pr) ? 1.0f : A[(size_t)pr * n + kk];
    }
    H[idx] = __float2half(v);   // small integers: exact
}

// B operand [kpN x kd] via 32x32 tiled transpose-gather (coalesced both sides):
// Bop[rnk[j]][kk] = A1[kk][j]; grid.y spans kd so K-padding columns get zeros.
__global__ void k_gBt(const float* __restrict__ A, int n, const int* __restrict__ rnk,
                      int kd, __half* __restrict__ H) {
    __shared__ float t[32][33];
    int j0 = blockIdx.x * 32, k0 = blockIdx.y * 32;
    int tx = threadIdx.x, ty = threadIdx.y;   // 32 x 8
    #pragma unroll
    for (int i = 0; i < 32; i += 8) {
        int kk = k0 + ty + i, j = j0 + tx;
        float v = 0.f;
        if (kk < n && j < n) v = (kk == j) ? 1.0f : A[(size_t)kk * n + j];
        t[ty + i][tx] = v;
    }
    __syncthreads();
    #pragma unroll
    for (int i = 0; i < 32; i += 8) {
        int j = j0 + ty + i, kk = k0 + tx;
        if (j < n && kk < kd) {
            int r = rnk[j];
            if (r >= 0) H[(size_t)r * kd + kk] = __float2half(t[tx][ty + i]);
        }
    }
}

// ---------------- level-1 sparse path ----------------
// Extract nonzeros of ALL A0 rows: one warp per row. diag(A0)=1 so A1==A0.
__global__ void k_extract_all(const float* __restrict__ A, int n,
                              int* __restrict__ nnzIdx, float* __restrict__ nnzVal,
                              int* __restrict__ nnzCnt) {
    int wid = threadIdx.x >> 5, lane = threadIdx.x & 31;
    int r = blockIdx.x * 8 + wid;
    if (r >= n) return;
    const float* row = A + (size_t)r * n;
    int cnt = 0;
    for (int j0 = 0; j0 < n; j0 += 32) {
        float v = row[j0 + lane];
        unsigned m = __ballot_sync(0xffffffffu, v != 0.f);
        if (v != 0.f) {
            int pos = cnt + __popc(m & ((1u << lane) - 1u));
            if (pos < CAP) {
                nnzIdx[(size_t)r * CAP + pos] = j0 + lane;
                nnzVal[(size_t)r * CAP + pos] = v;
            }
        }
        cnt += __popc(m);
    }
    if (lane == 0) nnzCnt[r] = min(cnt, CAP);
}

// Sparse x sparse: C[r][c] = sum_kk A0[perm[r]][kk] * A0[kk][perm[c]], diag zeroed.
// One block per output row; scatter into shared accumulator via rnk.
__global__ __launch_bounds__(256) void k_spmm_ss(
    const int* __restrict__ nnzIdx, const float* __restrict__ nnzVal,
    const int* __restrict__ nnzCnt,
    const int* __restrict__ perm, const int* __restrict__ rnk, int k,
    float* __restrict__ C, int ldc) {
    __shared__ float accum[KP1];
    __shared__ int   rIdx[CAP];
    __shared__ float rVal[CAP];
    int r = blockIdx.x;
    int pr = perm[r];
    for (int t = threadIdx.x; t < KP1; t += 256) accum[t] = 0.f;
    int cnt = nnzCnt[pr];
    for (int t = threadIdx.x; t < cnt; t += 256) {
        rIdx[t] = nnzIdx[(size_t)pr * CAP + t];
        rVal[t] = nnzVal[(size_t)pr * CAP + t];
    }
    __syncthreads();
    int wid = threadIdx.x >> 5, lane = threadIdx.x & 31;
    for (int j = wid; j < cnt; j += 8) {
        int kk = rIdx[j];
        float v = rVal[j];
        int c2 = nnzCnt[kk];
        const int*   ci = nnzIdx + (size_t)kk * CAP;
        const float* cv = nnzVal + (size_t)kk * CAP;
        for (int l = lane; l < c2; l += 32) {
            int rc = rnk[ci[l]];
            if (rc >= 0) atomicAdd(&accum[rc], v * cv[l]);   // exact integer adds
        }
    }
    __syncthreads();
    for (int t = threadIdx.x; t < k; t += 256)
        C[(size_t)r * ldc + t] = (t == r) ? 0.f : accum[t];
}

// ---------------- mma.sync fp16 GEMM: C = A @ B^T, 128x128 tile ----------------
#define BM 128
#define BN 128
#define BK 64
#define STG 3
#define LDS_H 72                      // padded halves/row: 144B = 9 x 16B
#define STAGE_HALVES (2 * 128 * LDS_H)
#define SMEM_HGEMM (STG * STAGE_HALVES * 2)   // 110592 bytes -> 2 CTAs/SM

__device__ __forceinline__ uint32_t smem_u32(const void* p) {
    uint32_t a;
    asm("{ .reg .u64 t; cvta.to.shared.u64 t, %1; cvt.u32.u64 %0, t; }"
        : "=r"(a) : "l"(p));
    return a;
}
__device__ __forceinline__ void cpa16(uint32_t s, const void* g) {
    asm volatile("cp.async.cg.shared.global [%0], [%1], 16;" :: "r"(s), "l"(g));
}
#define CP_COMMIT() asm volatile("cp.async.commit_group;" ::: "memory")
#define CP_WAIT(n)  asm volatile("cp.async.wait_group %0;" :: "n"(n) : "memory")

__device__ __forceinline__ void ldm_x4(uint32_t* r, uint32_t addr) {
    asm volatile("ldmatrix.sync.aligned.m8n8.x4.shared.b16 {%0,%1,%2,%3}, [%4];"
        : "=r"(r[0]), "=r"(r[1]), "=r"(r[2]), "=r"(r[3]) : "r"(addr));
}
__device__ __forceinline__ void mma16816(float* d, const uint32_t* a,
                                         uint32_t b0, uint32_t b1) {
    asm volatile("mma.sync.aligned.m16n8k16.row.col.f32.f16.f16.f32 "
        "{%0,%1,%2,%3}, {%4,%5,%6,%7}, {%8,%9}, {%0,%1,%2,%3};"
        : "+f"(d[0]), "+f"(d[1]), "+f"(d[2]), "+f"(d[3])
        : "r"(a[0]), "r"(a[1]), "r"(a[2]), "r"(a[3]), "r"(b0), "r"(b1));
}

// kd = row stride; kLen = this CTA's K extent (kOff = blockIdx.z * kLen).
// atomicOut: accumulate via exact-integer fp32 atomics (split-K), no diag logic.
__global__ __launch_bounds__(256, 2) void k_hgemm(
    int mreal, int nreal, int kd, int kLen,
    const __half* __restrict__ Ap, const __half* __restrict__ Bp,
    float* __restrict__ C, int ldc, int zeroDiag, int atomicOut)
{
    extern __shared__ __half sh[];
    const int tid = threadIdx.x;
    const int wid = tid >> 5, lane = tid & 31;
    const int bm = blockIdx.y * BM, bn = blockIdx.x * BN;
    const int wm0 = (wid & 3) * 32, wn0 = (wid >> 2) * 64;
    const int nch = kLen / BK;
    const int kOff = blockIdx.z * kLen;

    const __half* Ag = Ap + (size_t)bm * kd + kOff;
    const __half* Bg = Bp + (size_t)bn * kd + kOff;

    const int lc8 = tid & 7;          // 16B column within 64-half chunk
    const int lr0 = tid >> 3;         // base row

    float acc[2][8][4];
    #pragma unroll
    for (int mt = 0; mt < 2; mt++)
        #pragma unroll
        for (int n8 = 0; n8 < 8; n8++)
            #pragma unroll
            for (int q = 0; q < 4; q++) acc[mt][n8][q] = 0.f;

    // prologue: stages 0..STG-2
    #pragma unroll
    for (int s = 0; s < STG - 1; s++) {
        __half* sA = sh + s * STAGE_HALVES;
        __half* sB = sA + 128 * LDS_H;
        const __half* Asrc = Ag + s * BK;
        const __half* Bsrc = Bg + s * BK;
        #pragma unroll
        for (int i = 0; i < 4; i++) {
            int row = lr0 + i * 32;
            cpa16(smem_u32(&sA[row * LDS_H + lc8 * 8]), Asrc + (size_t)row * kd + lc8 * 8);
            cpa16(smem_u32(&sB[row * LDS_H + lc8 * 8]), Bsrc + (size_t)row * kd + lc8 * 8);
        }
        CP_COMMIT();
    }

    for (int c = 0; c < nch; c++) {
        CP_WAIT(STG - 2);
        __syncthreads();

        // prefetch chunk c+STG-1
        {
            int cf = c + STG - 1;
            if (cf < nch) {
                int s = cf % STG;
                __half* sA = sh + s * STAGE_HALVES;
                __half* sB = sA + 128 * LDS_H;
                const __half* Asrc = Ag + cf * BK;
                const __half* Bsrc = Bg + cf * BK;
                #pragma unroll
                for (int i = 0; i < 4; i++) {
                    int row = lr0 + i * 32;
                    cpa16(smem_u32(&sA[row * LDS_H + lc8 * 8]),
                          Asrc + (size_t)row * kd + lc8 * 8);
                    cpa16(smem_u32(&sB[row * LDS_H + lc8 * 8]),
                          Bsrc + (size_t)row * kd + lc8 * 8);
                }
            }
            CP_COMMIT();
        }

        // compute on stage c % STG
        {
            int s = c % STG;
            const __half* sA = sh + s * STAGE_HALVES;
            const __half* sB = sA + 128 * LDS_H;
            int ar = wm0 + (lane & 15);
            int ac = (lane >> 4) * 8;
            int br = wn0 + (lane & 7) + ((lane >> 4) & 1) * 8;
            int bc = ((lane >> 3) & 1) * 8;
            #pragma unroll
            for (int k16 = 0; k16 < 4; k16++) {
                uint32_t a[2][4];
                #pragma unroll
                for (int mt = 0; mt < 2; mt++)
                    ldm_x4(a[mt], smem_u32(&sA[(ar + mt * 16) * LDS_H + k16 * 16 + ac]));
                uint32_t b[4][4];
                #pragma unroll
                for (int ng = 0; ng < 4; ng++)
                    ldm_x4(b[ng], smem_u32(&sB[(br + ng * 16) * LDS_H + k16 * 16 + bc]));
                #pragma unroll
                for (int mt = 0; mt < 2; mt++)
                    #pragma unroll
                    for (int n8 = 0; n8 < 8; n8++) {
                        int ng = n8 >> 1, hi = (n8 & 1) << 1;
                        mma16816(acc[mt][n8], a[mt], b[ng][hi], b[ng][hi + 1]);
                    }
            }
        }
        __syncthreads();
    }

    // epilogue
    int g = lane >> 2, tg = lane & 3;
    #pragma unroll
    for (int mt = 0; mt < 2; mt++) {
        #pragma unroll
        for (int n8 = 0; n8 < 8; n8++) {
            int r1 = bm + wm0 + mt * 16 + g;
            int r2 = r1 + 8;
            int c0 = bn + wn0 + n8 * 8 + tg * 2;
            float* a4 = acc[mt][n8];
            if (atomicOut) {
                if (r1 < mreal) {
                    if (c0 < nreal)     atomicAdd(&C[(size_t)r1 * ldc + c0],     a4[0]);
                    if (c0 + 1 < nreal) atomicAdd(&C[(size_t)r1 * ldc + c0 + 1], a4[1]);
                }
                if (r2 < mreal) {
                    if (c0 < nreal)     atomicAdd(&C[(size_t)r2 * ldc + c0],     a4[2]);
                    if (c0 + 1 < nreal) atomicAdd(&C[(size_t)r2 * ldc + c0 + 1], a4[3]);
                }
            } else {
                if (r1 < mreal) {
                    if (c0 < nreal)
                        C[(size_t)r1 * ldc + c0] = (zeroDiag && r1 == c0) ? 0.f : a4[0];
                    if (c0 + 1 < nreal)
                        C[(size_t)r1 * ldc + c0 + 1] = (zeroDiag && r1 == c0 + 1) ? 0.f : a4[1];
                }
                if (r2 < mreal) {
                    if (c0 < nreal)
                        C[(size_t)r2 * ldc + c0] = (zeroDiag && r2 == c0) ? 0.f : a4[2];
                    if (c0 + 1 < nreal)
                        C[(size_t)r2 * ldc + c0 + 1] = (zeroDiag && r2 == c0 + 1) ? 0.f : a4[3];
                }
            }
        }
    }
}

// ---------------- host orchestration ----------------
struct DevPtrs {
    float *A0, *A1, *A2, *A3;
    __half *Ah, *Bh;
    float *x0, *x1, *x2, *x3, *xp, *y, *z, *part, *dpart, *score, *sval;
    float *dis[4], *slw[4];
    int *perm0, *perm1, *perm2, *rnk;
    int *nnzIdx; float *nnzVal; int *nnzCnt;
};
static DevPtrs P;
static bool g_init = false;

static void prep_deg(const float* A, int n, int lvl) {
    dim3 cs(cdiv(n, 256), DSPLIT);
    k_colsum<<<cs, 256>>>(A, n, P.dpart);
    k_degfin<<<cdiv(n, 256), 256>>>(A, n, P.dpart, P.dis[lvl], P.slw[lvl]);
}

// out: plain output (nullable). resAdd/perm: fused unpool. pvec: fused score.
template<int CIN, int COUT>
static void gcn(const float* A, int n, int lvl, const float* xin, const float* W,
                const float* b, bool relu, float* out,
                float* resAdd = nullptr, const int* perm = nullptr,
                const float* pvec = nullptr) {
    k_xw<CIN, COUT><<<cdiv(n * COUT, 256), 256>>>(xin, n, W, P.dis[lvl], P.y, P.z);
    dim3 ag(cdiv(n, 256), RSPLIT);
    k_atzp<COUT><<<ag, 256>>>(A, n, P.z, P.part);
    k_fin<COUT><<<cdiv(n * COUT, 256), 256>>>(n, P.part, P.y, P.dis[lvl], P.slw[lvl],
                                              b, relu ? 1 : 0, out, resAdd, perm,
                                              pvec, P.score);
}

static void pool_level(const float* A, int n, int k, int kp, int kd,
                       const float* x, int* perm, float* Anext,
                       bool sparse, int splitK) {
    // P.score already produced by the fused gcn fin
    k_rank2<<<cdiv(n, 256), 256>>>(P.score, n, k, perm, P.sval, P.rnk, x, P.xp);
    if (sparse) {
        k_extract_all<<<cdiv(n, 8), 256>>>(A, n, P.nnzIdx, P.nnzVal, P.nnzCnt);
        k_spmm_ss<<<k, 256>>>(P.nnzIdx, P.nnzVal, P.nnzCnt, perm, P.rnk, k, Anext, k);
    } else {
        dim3 tg(cdiv(n, 32), cdiv(kd, 32));
        k_gBt<<<tg, dim3(32, 8)>>>(A, n, P.rnk, kd, P.Bh);
        size_t tot = (size_t)kp * kd;
        k_gA<<<(int)((tot + 255) / 256), 256>>>(A, n, perm, k, kd, P.Ah);
        if (splitK > 1) k_zero<<<cdiv(k * k, 256), 256>>>(Anext, k * k);
        dim3 gg(kp / 128, kp / 128, splitK);
        k_hgemm<<<gg, 256, SMEM_HGEMM>>>(k, k, kd, kd / splitK, P.Ah, P.Bh, Anext, k,
                                         splitK > 1 ? 0 : 1, splitK > 1 ? 1 : 0);
        if (splitK > 1) k_zdiag<<<cdiv(k, 256), 256>>>(Anext, k);
    }
}

extern "C" void kernel_launch(void* const* d_in, const int* in_sizes, int n_in,
                              void* d_out, int out_size) {
    if (!g_init) {
        cudaGetSymbolAddress((void**)&P.A0, g_A0);
        cudaGetSymbolAddress((void**)&P.A1, g_A1);
        cudaGetSymbolAddress((void**)&P.A2, g_A2);
        cudaGetSymbolAddress((void**)&P.A3, g_A3);
        cudaGetSymbolAddress((void**)&P.Ah, g_Ah);
        cudaGetSymbolAddress((void**)&P.Bh, g_Bh);
        cudaGetSymbolAddress((void**)&P.x0, g_x0);
        cudaGetSymbolAddress((void**)&P.x1, g_x1);
        cudaGetSymbolAddress((void**)&P.x2, g_x2);
        cudaGetSymbolAddress((void**)&P.x3, g_x3);
        cudaGetSymbolAddress((void**)&P.xp, g_xp);
        cudaGetSymbolAddress((void**)&P.y,  g_y);
        cudaGetSymbolAddress((void**)&P.z,  g_z);
        cudaGetSymbolAddress((void**)&P.part,  g_part);
        cudaGetSymbolAddress((void**)&P.dpart, g_dpart);
        float* disBase; float* slwBase;
        cudaGetSymbolAddress((void**)&disBase, g_disA);
        cudaGetSymbolAddress((void**)&slwBase, g_slwA);
        for (int l = 0; l < 4; l++) { P.dis[l] = disBase + l * N0; P.slw[l] = slwBase + l * N0; }
        cudaGetSymbolAddress((void**)&P.score, g_score);
        cudaGetSymbolAddress((void**)&P.sval,  g_sval);
        cudaGetSymbolAddress((void**)&P.perm0, g_perm0);
        cudaGetSymbolAddress((void**)&P.perm1, g_perm1);
        cudaGetSymbolAddress((void**)&P.perm2, g_perm2);
        cudaGetSymbolAddress((void**)&P.rnk,   g_rnk);
        cudaGetSymbolAddress((void**)&P.nnzIdx, g_nnzIdx);
        cudaGetSymbolAddress((void**)&P.nnzVal, g_nnzVal);
        cudaGetSymbolAddress((void**)&P.nnzCnt, g_nnzCnt);
        cudaFuncSetAttribute(k_hgemm, cudaFuncAttributeMaxDynamicSharedMemorySize,
                             SMEM_HGEMM);
        g_init = true;
    }

    const float* x_in = (const float*)d_in[0];
    const int*   ei   = (const int*)d_in[1];
    const float* W0 = (const float*)d_in[2];  const float* b0 = (const float*)d_in[3];
    const float* W1 = (const float*)d_in[4];  const float* b1 = (const float*)d_in[5];
    const float* W2 = (const float*)d_in[6];  const float* b2 = (const float*)d_in[7];
    const float* W3 = (const float*)d_in[8];  const float* b3 = (const float*)d_in[9];
    const float* p1 = (const float*)d_in[10];
    const float* p2 = (const float*)d_in[11];
    const float* p3 = (const float*)d_in[12];
    const float* U0 = (const float*)d_in[13]; const float* c0 = (const float*)d_in[14];
    const float* U1 = (const float*)d_in[15]; const float* c1 = (const float*)d_in[16];
    const float* U2 = (const float*)d_in[17]; const float* c2 = (const float*)d_in[18];
    float* out = (float*)d_out;

    // A0 = dense adjacency with parallel-edge accumulation + unit self loops
    k_zero<<<cdiv(N0 * N0, 256), 256>>>(P.A0, N0 * N0);
    k_edges<<<cdiv(EDG, 256), 256>>>(ei, ei + EDG, P.A0);
    k_diag1<<<cdiv(N0, 256), 256>>>(P.A0);

    // ---- down path ----
    prep_deg(P.A0, N0, 0);
    gcn<20, 64>(P.A0, N0, 0, x_in, W0, b0, true, P.x0, nullptr, nullptr, p1);

    // level 1: sparse x sparse augment product
    pool_level(P.A0, N0, K1, KP1, KD1, P.x0, P.perm0, P.A1, true, 1);
    prep_deg(P.A1, K1, 1);
    gcn<64, 64>(P.A1, K1, 1, P.xp, W1, b1, true, P.x1, nullptr, nullptr, p2);

    // level 2: dense fp16 GEMM, split-K=2 (wave-quantization fix; exact atomics)
    pool_level(P.A1, K1, K2, KP2, KD2, P.x1, P.perm1, P.A2, false, 2);
    prep_deg(P.A2, K2, 2);
    gcn<64, 64>(P.A2, K2, 2, P.xp, W2, b2, true, P.x2, nullptr, nullptr, p3);

    // level 3: dense fp16 GEMM (289 CTAs ~ 1 wave, no split)
    pool_level(P.A2, K2, K3, KP3, KD3, P.x2, P.perm2, P.A3, false, 1);
    prep_deg(P.A3, K3, 3);
    // fused unpool: x2[perm2] += relu(conv(A3, xp))
    gcn<64, 64>(P.A3, K3, 3, P.xp, W3, b3, true, nullptr, P.x2, P.perm2);

    // ---- up path (degrees reused; unpool fused into fin) ----
    gcn<64, 64>(P.A2, K2, 2, P.x2, U0, c0, true, nullptr, P.x1, P.perm1);
    gcn<64, 64>(P.A1, K1, 1, P.x1, U1, c1, true, nullptr, P.x0, P.perm0);
    gcn<64, 20>(P.A0, N0, 0, P.x0, U2, c2, false, out);
}

// round 17
// speedup vs baseline: 1.2587x; 1.0029x over previous
#include <cuda_runtime.h>
#include <cuda_fp16.h>
#include <math.h>
#include <stdint.h>

// ---------------- problem constants ----------------
#define N0   4096
#define EDG  131072
#define K1   3277      // ceil(0.8*4096)
#define K2   2622      // ceil(0.8*3277)
#define K3   2098      // ceil(0.8*2622)
#define KP1  3328      // K1 padded to 128 (GEMM M/N tiles)
#define KP2  2688
#define KP3  2176
#define KD1  4096      // GEMM K dim padded to 64
#define KD2  3328
#define KD3  2624
#define CH   64
#define DSPLIT 32
#define RSPLIT 16
#define CAP  256       // max nnz per A0 row (Poisson(32); P(>255) ~ 0)

// ---------------- device scratch (no allocation allowed) ----------------
__device__ float g_A0[(size_t)N0*N0];
__device__ float g_A1[(size_t)K1*K1];
__device__ float g_A2[(size_t)K2*K2];
__device__ float g_A3[(size_t)K3*K3];
__device__ __half g_Ah[(size_t)KP1*KD1];   // dense GEMM A operand
__device__ __half g_Bh[(size_t)KP1*KD1];   // GEMM operand B, [N,K] row-major
__device__ float g_x0[N0*CH];
__device__ float g_x1[K1*CH];
__device__ float g_x2[K2*CH];
__device__ float g_x3[K3*CH];
__device__ float g_xp[N0*CH];
__device__ float g_y [N0*CH];
__device__ float g_z [N0*CH];
__device__ float g_part [(size_t)RSPLIT*N0*CH];
__device__ float g_dpart[(size_t)DSPLIT*N0];
__device__ float g_deg[N0];
__device__ float g_disA[4][N0];
__device__ float g_slwA[4][N0];
__device__ float g_score[N0];
__device__ float g_sval[N0];
__device__ int   g_perm0[K1];
__device__ int   g_perm1[K2];
__device__ int   g_perm2[K3];
__device__ int   g_rnk[N0];
__device__ int   g_nnzIdx[(size_t)N0*CAP];   // CSR of ALL A0 rows
__device__ float g_nnzVal[(size_t)N0*CAP];
__device__ int   g_nnzCnt[N0];

static inline int cdiv(int a, int b) { return (a + b - 1) / b; }

// ---------------- elementwise ----------------
__global__ void k_zero(float* p, int n) {
    int i = blockIdx.x * blockDim.x + threadIdx.x;
    if (i < n) p[i] = 0.f;
}

__global__ void k_edges(const int* __restrict__ src, const int* __restrict__ dst,
                        float* __restrict__ A) {
    int i = blockIdx.x * blockDim.x + threadIdx.x;
    if (i >= EDG) return;
    int s = src[i], d = dst[i];
    if (s != d) atomicAdd(&A[(size_t)s * N0 + d], 1.0f);   // exact integer adds
}

__global__ void k_diag1(float* A) {
    int i = blockIdx.x * blockDim.x + threadIdx.x;
    if (i < N0) A[(size_t)i * N0 + i] += 1.0f;
}

__global__ void k_zdiag(float* A, int n) {
    int i = blockIdx.x * blockDim.x + threadIdx.x;
    if (i < n) A[(size_t)i * n + i] = 0.f;
}

// ---------------- degree / normalization ----------------
__global__ void k_colsum(const float* __restrict__ A, int n, float* __restrict__ dpart) {
    int c = blockIdx.x * blockDim.x + threadIdx.x;
    if (c >= n) return;
    int chunk = (n + DSPLIT - 1) / DSPLIT;
    int r0 = blockIdx.y * chunk;
    int r1 = min(n, r0 + chunk);
    float s = 0.f;
    for (int r = r0; r < r1; r++) s += A[(size_t)r * n + c];
    dpart[(size_t)blockIdx.y * n + c] = s;
}

__global__ void k_degfin(const float* __restrict__ A, int n,
                         const float* __restrict__ dpart,
                         float* __restrict__ dis, float* __restrict__ slw) {
    int c = blockIdx.x * blockDim.x + threadIdx.x;
    if (c >= n) return;
    float s = 0.f;
    for (int q = 0; q < DSPLIT; q++) s += dpart[(size_t)q * n + c];
    float dg = A[(size_t)c * n + c];
    float sl = (dg == 0.f) ? 2.f : 0.f;    // add_remaining_self_loops, fill=2
    float deg = s + sl;
    slw[c] = sl;
    dis[c] = (deg > 0.f) ? rsqrtf(deg) : 0.f;
}

// Finalize degree from the GEMM-accumulated column sums (augmented A: diag=0 -> sl=2)
__global__ void k_degfin2(const float* __restrict__ deg, int n,
                          float* __restrict__ dis, float* __restrict__ slw) {
    int c = blockIdx.x * blockDim.x + threadIdx.x;
    if (c >= n) return;
    float d = deg[c] + 2.f;
    slw[c] = 2.f;
    dis[c] = (d > 0.f) ? rsqrtf(d) : 0.f;
}

// ---------------- x @ W, scaled by dis ----------------
template<int CIN, int COUT>
__global__ void k_xw(const float* __restrict__ x, int n, const float* __restrict__ W,
                     const float* __restrict__ dis,
                     float* __restrict__ y, float* __restrict__ z) {
    int idx = blockIdx.x * blockDim.x + threadIdx.x;
    if (idx >= n * COUT) return;
    int r = idx / COUT, j = idx % COUT;
    float s = 0.f;
    #pragma unroll
    for (int k = 0; k < CIN; k++) s += x[(size_t)r * CIN + k] * W[k * COUT + j];
    y[idx] = s;
    z[idx] = dis[r] * s;
}

// ---------------- out_part = (A^T z) split over rows ----------------
template<int COUT>
__global__ void k_atzp(const float* __restrict__ A, int n,
                       const float* __restrict__ z, float* __restrict__ part) {
    const int RC = 8;
    __shared__ float zs[RC][COUT];
    int c = blockIdx.x * blockDim.x + threadIdx.x;
    int chunk = (n + RSPLIT - 1) / RSPLIT;
    int r0b = blockIdx.y * chunk;
    int r1  = min(n, r0b + chunk);
    float acc[COUT];
    #pragma unroll
    for (int j = 0; j < COUT; j++) acc[j] = 0.f;
    for (int r0 = r0b; r0 < r1; r0 += RC) {
        __syncthreads();
        for (int t = threadIdx.x; t < RC * COUT; t += blockDim.x) {
            int rr = t / COUT, j = t % COUT;
            int r = r0 + rr;
            zs[rr][j] = (r < r1) ? z[(size_t)r * COUT + j] : 0.f;
        }
        __syncthreads();
        int rmax = min(RC, r1 - r0);
        if (c < n) {
            for (int rr = 0; rr < rmax; rr++) {
                float a = A[(size_t)(r0 + rr) * n + c];
                #pragma unroll
                for (int j = 0; j < COUT; j++) acc[j] += a * zs[rr][j];
            }
        }
    }
    if (c < n) {
        #pragma unroll
        for (int j = 0; j < COUT; j++)
            part[((size_t)blockIdx.y * n + c) * COUT + j] = acc[j];
    }
}

// Finalize conv + optional fused unpool (resAdd) + optional fused score.
template<int COUT>
__global__ void k_fin(int n, const float* __restrict__ part,
                      const float* __restrict__ y, const float* __restrict__ dis,
                      const float* __restrict__ slw, const float* __restrict__ b,
                      int doRelu, float* __restrict__ out,
                      float* __restrict__ resAdd, const int* __restrict__ perm,
                      const float* __restrict__ p, float* __restrict__ score) {
    __shared__ float sp[COUT];
    __shared__ float sv[256];
    int idx = blockIdx.x * 256 + threadIdx.x;
    bool valid = idx < n * COUT;
    int c = idx / COUT, j = idx - c * COUT;
    if (p && threadIdx.x < COUT) sp[threadIdx.x] = p[threadIdx.x];
    float v = 0.f;
    if (valid) {
        float s = 0.f;
        for (int q = 0; q < RSPLIT; q++) s += part[((size_t)q * n + c) * COUT + j];
        float dc = dis[c];
        v = dc * (s + slw[c] * dc * y[idx]) + b[j];
        if (doRelu) v = fmaxf(v, 0.f);
        if (out) out[idx] = v;
        if (resAdd) resAdd[(size_t)perm[c] * COUT + j] += v;  // unique (c,j): race-free
    }
    if (p) {
        sv[threadIdx.x] = valid ? v : 0.f;
        __syncthreads();
        int w = threadIdx.x;
        if (w < 256 / COUT) {
            int row = blockIdx.x * (256 / COUT) + w;
            if (row < n) {
                float pp = 0.f, dot = 0.f;
                for (int k2 = 0; k2 < COUT; k2++) {
                    float pk = sp[k2];
                    pp  += pk * pk;
                    dot += sv[w * COUT + k2] * pk;
                }
                score[row] = tanhf(dot / sqrtf(pp));
            }
        }
    }
}

// Fused: rank + perm + sval + inverse-perm + pooled features
__global__ void k_rank2(const float* __restrict__ score, int n, int k,
                        int* __restrict__ perm, float* __restrict__ sval,
                        int* __restrict__ rnk,
                        const float* __restrict__ x, float* __restrict__ xp) {
    __shared__ float ss[1024];
    int i = blockIdx.x * blockDim.x + threadIdx.x;
    float si = (i < n) ? score[i] : 0.f;
    int rank = 0;
    for (int j0 = 0; j0 < n; j0 += 1024) {
        int cnt = min(1024, n - j0);
        __syncthreads();
        for (int t = threadIdx.x; t < cnt; t += blockDim.x) ss[t] = score[j0 + t];
        __syncthreads();
        if (i < n) {
            for (int jj = 0; jj < cnt; jj++) {
                float sj = ss[jj];
                int j = j0 + jj;
                rank += (sj > si) || (sj == si && j < i);
            }
        }
    }
    if (i < n) {
        if (rank < k) {
            perm[rank] = i;
            sval[rank] = si;
            rnk[i] = rank;
            const float4* xr = (const float4*)(x + (size_t)i * CH);
            float4* xo = (float4*)(xp + (size_t)rank * CH);
            #pragma unroll
            for (int q = 0; q < CH / 4; q++) {
                float4 v = xr[q];
                v.x *= si; v.y *= si; v.z *= si; v.w *= si;
                xo[q] = v;
            }
        } else {
            rnk[i] = -1;
        }
    }
}

// ---------------- fused operand gather ----------------
// One pass over A produces BOTH fp16 GEMM operands:
//   Aop[rnk[kk]][j] = A1[kk][j]      (straight copy, coalesced along j)
//   Bop[rnk[j]][kk] = A1[kk][j]      (via shared-memory transpose)
// grid spans cdiv(kd,32) x cdiv(kd,32); out-of-range reads produce zeros -> padding.
__global__ void k_gAB(const float* __restrict__ A, int n, const int* __restrict__ rnk,
                      int kd, __half* __restrict__ Aop, __half* __restrict__ Bop) {
    __shared__ float t[32][33];
    int j0 = blockIdx.x * 32, k0 = blockIdx.y * 32;
    int tx = threadIdx.x, ty = threadIdx.y;   // 32 x 8
    #pragma unroll
    for (int i = 0; i < 32; i += 8) {
        int kk = k0 + ty + i, j = j0 + tx;
        float v = 0.f;
        if (kk < n && j < n) v = (kk == j) ? 1.0f : A[(size_t)kk * n + j];
        t[ty + i][tx] = v;
        if (kk < n && j < kd) {
            int r = rnk[kk];
            if (r >= 0) Aop[(size_t)r * kd + j] = __float2half(v);
        }
    }
    __syncthreads();
    #pragma unroll
    for (int i = 0; i < 32; i += 8) {
        int j = j0 + ty + i, kk = k0 + tx;
        if (j < n && kk < kd) {
            int r = rnk[j];
            if (r >= 0) Bop[(size_t)r * kd + kk] = __float2half(t[tx][ty + i]);
        }
    }
}

// ---------------- level-1 sparse path ----------------
__global__ void k_extract_all(const float* __restrict__ A, int n,
                              int* __restrict__ nnzIdx, float* __restrict__ nnzVal,
                              int* __restrict__ nnzCnt) {
    int wid = threadIdx.x >> 5, lane = threadIdx.x & 31;
    int r = blockIdx.x * 8 + wid;
    if (r >= n) return;
    const float* row = A + (size_t)r * n;
    int cnt = 0;
    for (int j0 = 0; j0 < n; j0 += 32) {
        float v = row[j0 + lane];
        unsigned m = __ballot_sync(0xffffffffu, v != 0.f);
        if (v != 0.f) {
            int pos = cnt + __popc(m & ((1u << lane) - 1u));
            if (pos < CAP) {
                nnzIdx[(size_t)r * CAP + pos] = j0 + lane;
                nnzVal[(size_t)r * CAP + pos] = v;
            }
        }
        cnt += __popc(m);
    }
    if (lane == 0) nnzCnt[r] = min(cnt, CAP);
}

// Sparse x sparse level-1 product (exact integer adds)
__global__ __launch_bounds__(256) void k_spmm_ss(
    const int* __restrict__ nnzIdx, const float* __restrict__ nnzVal,
    const int* __restrict__ nnzCnt,
    const int* __restrict__ perm, const int* __restrict__ rnk, int k,
    float* __restrict__ C, int ldc) {
    __shared__ float accum[KP1];
    __shared__ int   rIdx[CAP];
    __shared__ float rVal[CAP];
    int r = blockIdx.x;
    int pr = perm[r];
    for (int t = threadIdx.x; t < KP1; t += 256) accum[t] = 0.f;
    int cnt = nnzCnt[pr];
    for (int t = threadIdx.x; t < cnt; t += 256) {
        rIdx[t] = nnzIdx[(size_t)pr * CAP + t];
        rVal[t] = nnzVal[(size_t)pr * CAP + t];
    }
    __syncthreads();
    int wid = threadIdx.x >> 5, lane = threadIdx.x & 31;
    for (int j = wid; j < cnt; j += 8) {
        int kk = rIdx[j];
        float v = rVal[j];
        int c2 = nnzCnt[kk];
        const int*   ci = nnzIdx + (size_t)kk * CAP;
        const float* cv = nnzVal + (size_t)kk * CAP;
        for (int l = lane; l < c2; l += 32) {
            int rc = rnk[ci[l]];
            if (rc >= 0) atomicAdd(&accum[rc], v * cv[l]);
        }
    }
    __syncthreads();
    for (int t = threadIdx.x; t < k; t += 256)
        C[(size_t)r * ldc + t] = (t == r) ? 0.f : accum[t];
}

// ---------------- mma.sync fp16 GEMM: C = A @ B^T, 128x128 tile ----------------
#define BM 128
#define BN 128
#define BK 64
#define STG 3
#define LDS_H 72
#define STAGE_HALVES (2 * 128 * LDS_H)
#define SMEM_HGEMM (STG * STAGE_HALVES * 2)   // 110592 bytes -> 2 CTAs/SM

__device__ __forceinline__ uint32_t smem_u32(const void* p) {
    uint32_t a;
    asm("{ .reg .u64 t; cvta.to.shared.u64 t, %1; cvt.u32.u64 %0, t; }"
        : "=r"(a) : "l"(p));
    return a;
}
__device__ __forceinline__ void cpa16(uint32_t s, const void* g) {
    asm volatile("cp.async.cg.shared.global [%0], [%1], 16;" :: "r"(s), "l"(g));
}
#define CP_COMMIT() asm volatile("cp.async.commit_group;" ::: "memory")
#define CP_WAIT(n)  asm volatile("cp.async.wait_group %0;" :: "n"(n) : "memory")

__device__ __forceinline__ void ldm_x4(uint32_t* r, uint32_t addr) {
    asm volatile("ldmatrix.sync.aligned.m8n8.x4.shared.b16 {%0,%1,%2,%3}, [%4];"
        : "=r"(r[0]), "=r"(r[1]), "=r"(r[2]), "=r"(r[3]) : "r"(addr));
}
__device__ __forceinline__ void mma16816(float* d, const uint32_t* a,
                                         uint32_t b0, uint32_t b1) {
    asm volatile("mma.sync.aligned.m16n8k16.row.col.f32.f16.f16.f32 "
        "{%0,%1,%2,%3}, {%4,%5,%6,%7}, {%8,%9}, {%0,%1,%2,%3};"
        : "+f"(d[0]), "+f"(d[1]), "+f"(d[2]), "+f"(d[3])
        : "r"(a[0]), "r"(a[1]), "r"(a[2]), "r"(a[3]), "r"(b0), "r"(b1));
}

// deg != nullptr: also atomically accumulate column sums (excluding diagonal) --
// exact because all products/sums are small integers.
__global__ __launch_bounds__(256, 2) void k_hgemm(
    int mreal, int nreal, int kd, int kLen,
    const __half* __restrict__ Ap, const __half* __restrict__ Bp,
    float* __restrict__ C, int ldc, int zeroDiag, int atomicOut,
    float* __restrict__ deg)
{
    extern __shared__ __half sh[];
    const int tid = threadIdx.x;
    const int wid = tid >> 5, lane = tid & 31;
    const int bm = blockIdx.y * BM, bn = blockIdx.x * BN;
    const int wm0 = (wid & 3) * 32, wn0 = (wid >> 2) * 64;
    const int nch = kLen / BK;
    const int kOff = blockIdx.z * kLen;

    const __half* Ag = Ap + (size_t)bm * kd + kOff;
    const __half* Bg = Bp + (size_t)bn * kd + kOff;

    const int lc8 = tid & 7;
    const int lr0 = tid >> 3;

    float acc[2][8][4];
    #pragma unroll
    for (int mt = 0; mt < 2; mt++)
        #pragma unroll
        for (int n8 = 0; n8 < 8; n8++)
            #pragma unroll
            for (int q = 0; q < 4; q++) acc[mt][n8][q] = 0.f;

    #pragma unroll
    for (int s = 0; s < STG - 1; s++) {
        __half* sA = sh + s * STAGE_HALVES;
        __half* sB = sA + 128 * LDS_H;
        const __half* Asrc = Ag + s * BK;
        const __half* Bsrc = Bg + s * BK;
        #pragma unroll
        for (int i = 0; i < 4; i++) {
            int row = lr0 + i * 32;
            cpa16(smem_u32(&sA[row * LDS_H + lc8 * 8]), Asrc + (size_t)row * kd + lc8 * 8);
            cpa16(smem_u32(&sB[row * LDS_H + lc8 * 8]), Bsrc + (size_t)row * kd + lc8 * 8);
        }
        CP_COMMIT();
    }

    for (int c = 0; c < nch; c++) {
        CP_WAIT(STG - 2);
        __syncthreads();

        {
            int cf = c + STG - 1;
            if (cf < nch) {
                int s = cf % STG;
                __half* sA = sh + s * STAGE_HALVES;
                __half* sB = sA + 128 * LDS_H;
                const __half* Asrc = Ag + cf * BK;
                const __half* Bsrc = Bg + cf * BK;
                #pragma unroll
                for (int i = 0; i < 4; i++) {
                    int row = lr0 + i * 32;
                    cpa16(smem_u32(&sA[row * LDS_H + lc8 * 8]),
                          Asrc + (size_t)row * kd + lc8 * 8);
                    cpa16(smem_u32(&sB[row * LDS_H + lc8 * 8]),
                          Bsrc + (size_t)row * kd + lc8 * 8);
                }
            }
            CP_COMMIT();
        }

        {
            int s = c % STG;
            const __half* sA = sh + s * STAGE_HALVES;
            const __half* sB = sA + 128 * LDS_H;
            int ar = wm0 + (lane & 15);
            int ac = (lane >> 4) * 8;
            int br = wn0 + (lane & 7) + ((lane >> 4) & 1) * 8;
            int bc = ((lane >> 3) & 1) * 8;
            #pragma unroll
            for (int k16 = 0; k16 < 4; k16++) {
                uint32_t a[2][4];
                #pragma unroll
                for (int mt = 0; mt < 2; mt++)
                    ldm_x4(a[mt], smem_u32(&sA[(ar + mt * 16) * LDS_H + k16 * 16 + ac]));
                uint32_t b[4][4];
                #pragma unroll
                for (int ng = 0; ng < 4; ng++)
                    ldm_x4(b[ng], smem_u32(&sB[(br + ng * 16) * LDS_H + k16 * 16 + bc]));
                #pragma unroll
                for (int mt = 0; mt < 2; mt++)
                    #pragma unroll
                    for (int n8 = 0; n8 < 8; n8++) {
                        int ng = n8 >> 1, hi = (n8 & 1) << 1;
                        mma16816(acc[mt][n8], a[mt], b[ng][hi], b[ng][hi + 1]);
                    }
            }
        }
        __syncthreads();
    }

    // epilogue (+ optional fused column sums, diag excluded)
    int g = lane >> 2, tg = lane & 3;
    #pragma unroll
    for (int mt = 0; mt < 2; mt++) {
        #pragma unroll
        for (int n8 = 0; n8 < 8; n8++) {
            int r1 = bm + wm0 + mt * 16 + g;
            int r2 = r1 + 8;
            int c0 = bn + wn0 + n8 * 8 + tg * 2;
            float* a4 = acc[mt][n8];
            if (atomicOut) {
                if (r1 < mreal) {
                    if (c0 < nreal)     atomicAdd(&C[(size_t)r1 * ldc + c0],     a4[0]);
                    if (c0 + 1 < nreal) atomicAdd(&C[(size_t)r1 * ldc + c0 + 1], a4[1]);
                }
                if (r2 < mreal) {
                    if (c0 < nreal)     atomicAdd(&C[(size_t)r2 * ldc + c0],     a4[2]);
                    if (c0 + 1 < nreal) atomicAdd(&C[(size_t)r2 * ldc + c0 + 1], a4[3]);
                }
            } else {
                if (r1 < mreal) {
                    if (c0 < nreal)
                        C[(size_t)r1 * ldc + c0] = (zeroDiag && r1 == c0) ? 0.f : a4[0];
                    if (c0 + 1 < nreal)
                        C[(size_t)r1 * ldc + c0 + 1] = (zeroDiag && r1 == c0 + 1) ? 0.f : a4[1];
                }
                if (r2 < mreal) {
                    if (c0 < nreal)
                        C[(size_t)r2 * ldc + c0] = (zeroDiag && r2 == c0) ? 0.f : a4[2];
                    if (c0 + 1 < nreal)
                        C[(size_t)r2 * ldc + c0 + 1] = (zeroDiag && r2 == c0 + 1) ? 0.f : a4[3];
                }
            }
            if (deg) {
                float s0 = 0.f, s1 = 0.f;
                if (r1 < mreal) {
                    if (r1 != c0)     s0 += a4[0];
                    if (r1 != c0 + 1) s1 += a4[1];
                }
                if (r2 < mreal) {
                    if (r2 != c0)     s0 += a4[2];
                    if (r2 != c0 + 1) s1 += a4[3];
                }
                if (c0 < nreal && s0 != 0.f)     atomicAdd(&deg[c0],     s0);
                if (c0 + 1 < nreal && s1 != 0.f) atomicAdd(&deg[c0 + 1], s1);
            }
        }
    }
}

// ---------------- host orchestration ----------------
struct DevPtrs {
    float *A0, *A1, *A2, *A3;
    __half *Ah, *Bh;
    float *x0, *x1, *x2, *x3, *xp, *y, *z, *part, *dpart, *deg, *score, *sval;
    float *dis[4], *slw[4];
    int *perm0, *perm1, *perm2, *rnk;
    int *nnzIdx; float *nnzVal; int *nnzCnt;
};
static DevPtrs P;
static bool g_init = false;

static void prep_deg(const float* A, int n, int lvl) {
    dim3 cs(cdiv(n, 256), DSPLIT);
    k_colsum<<<cs, 256>>>(A, n, P.dpart);
    k_degfin<<<cdiv(n, 256), 256>>>(A, n, P.dpart, P.dis[lvl], P.slw[lvl]);
}

template<int CIN, int COUT>
static void gcn(const float* A, int n, int lvl, const float* xin, const float* W,
                const float* b, bool relu, float* out,
                float* resAdd = nullptr, const int* perm = nullptr,
                const float* pvec = nullptr) {
    k_xw<CIN, COUT><<<cdiv(n * COUT, 256), 256>>>(xin, n, W, P.dis[lvl], P.y, P.z);
    dim3 ag(cdiv(n, 256), RSPLIT);
    k_atzp<COUT><<<ag, 256>>>(A, n, P.z, P.part);
    k_fin<COUT><<<cdiv(n * COUT, 256), 256>>>(n, P.part, P.y, P.dis[lvl], P.slw[lvl],
                                              b, relu ? 1 : 0, out, resAdd, perm,
                                              pvec, P.score);
}

// dense levels: fused A/B operand gather + GEMM with fused column sums (deg)
static void pool_level(const float* A, int n, int k, int kp, int kd,
                       const float* x, int* perm, float* Anext,
                       bool sparse, int splitK, int lvl) {
    k_rank2<<<cdiv(n, 256), 256>>>(P.score, n, k, perm, P.sval, P.rnk, x, P.xp);
    if (sparse) {
        k_extract_all<<<cdiv(n, 8), 256>>>(A, n, P.nnzIdx, P.nnzVal, P.nnzCnt);
        k_spmm_ss<<<k, 256>>>(P.nnzIdx, P.nnzVal, P.nnzCnt, perm, P.rnk, k, Anext, k);
    } else {
        dim3 tg(cdiv(kd, 32), cdiv(kd, 32));
        k_gAB<<<tg, dim3(32, 8)>>>(A, n, P.rnk, kd, P.Ah, P.Bh);
        k_zero<<<cdiv(k, 256), 256>>>(P.deg, k);
        if (splitK > 1) k_zero<<<cdiv(k * k, 256), 256>>>(Anext, k * k);
        dim3 gg(kp / 128, kp / 128, splitK);
        k_hgemm<<<gg, 256, SMEM_HGEMM>>>(k, k, kd, kd / splitK, P.Ah, P.Bh, Anext, k,
                                         splitK > 1 ? 0 : 1, splitK > 1 ? 1 : 0, P.deg);
        if (splitK > 1) k_zdiag<<<cdiv(k, 256), 256>>>(Anext, k);
        // degree directly from fused column sums (augmented A: slw=2 everywhere)
        k_degfin2<<<cdiv(k, 256), 256>>>(P.deg, k, P.dis[lvl], P.slw[lvl]);
    }
}

extern "C" void kernel_launch(void* const* d_in, const int* in_sizes, int n_in,
                              void* d_out, int out_size) {
    if (!g_init) {
        cudaGetSymbolAddress((void**)&P.A0, g_A0);
        cudaGetSymbolAddress((void**)&P.A1, g_A1);
        cudaGetSymbolAddress((void**)&P.A2, g_A2);
        cudaGetSymbolAddress((void**)&P.A3, g_A3);
        cudaGetSymbolAddress((void**)&P.Ah, g_Ah);
        cudaGetSymbolAddress((void**)&P.Bh, g_Bh);
        cudaGetSymbolAddress((void**)&P.x0, g_x0);
        cudaGetSymbolAddress((void**)&P.x1, g_x1);
        cudaGetSymbolAddress((void**)&P.x2, g_x2);
        cudaGetSymbolAddress((void**)&P.x3, g_x3);
        cudaGetSymbolAddress((void**)&P.xp, g_xp);
        cudaGetSymbolAddress((void**)&P.y,  g_y);
        cudaGetSymbolAddress((void**)&P.z,  g_z);
        cudaGetSymbolAddress((void**)&P.part,  g_part);
        cudaGetSymbolAddress((void**)&P.dpart, g_dpart);
        cudaGetSymbolAddress((void**)&P.deg,   g_deg);
        float* disBase; float* slwBase;
        cudaGetSymbolAddress((void**)&disBase, g_disA);
        cudaGetSymbolAddress((void**)&slwBase, g_slwA);
        for (int l = 0; l < 4; l++) { P.dis[l] = disBase + l * N0; P.slw[l] = slwBase + l * N0; }
        cudaGetSymbolAddress((void**)&P.score, g_score);
        cudaGetSymbolAddress((void**)&P.sval,  g_sval);
        cudaGetSymbolAddress((void**)&P.perm0, g_perm0);
        cudaGetSymbolAddress((void**)&P.perm1, g_perm1);
        cudaGetSymbolAddress((void**)&P.perm2, g_perm2);
        cudaGetSymbolAddress((void**)&P.rnk,   g_rnk);
        cudaGetSymbolAddress((void**)&P.nnzIdx, g_nnzIdx);
        cudaGetSymbolAddress((void**)&P.nnzVal, g_nnzVal);
        cudaGetSymbolAddress((void**)&P.nnzCnt, g_nnzCnt);
        cudaFuncSetAttribute(k_hgemm, cudaFuncAttributeMaxDynamicSharedMemorySize,
                             SMEM_HGEMM);
        g_init = true;
    }

    const float* x_in = (const float*)d_in[0];
    const int*   ei   = (const int*)d_in[1];
    const float* W0 = (const float*)d_in[2];  const float* b0 = (const float*)d_in[3];
    const float* W1 = (const float*)d_in[4];  const float* b1 = (const float*)d_in[5];
    const float* W2 = (const float*)d_in[6];  const float* b2 = (const float*)d_in[7];
    const float* W3 = (const float*)d_in[8];  const float* b3 = (const float*)d_in[9];
    const float* p1 = (const float*)d_in[10];
    const float* p2 = (const float*)d_in[11];
    const float* p3 = (const float*)d_in[12];
    const float* U0 = (const float*)d_in[13]; const float* c0 = (const float*)d_in[14];
    const float* U1 = (const float*)d_in[15]; const float* c1 = (const float*)d_in[16];
    const float* U2 = (const float*)d_in[17]; const float* c2 = (const float*)d_in[18];
    float* out = (float*)d_out;

    // A0 = dense adjacency with parallel-edge accumulation + unit self loops
    k_zero<<<cdiv(N0 * N0, 256), 256>>>(P.A0, N0 * N0);
    k_edges<<<cdiv(EDG, 256), 256>>>(ei, ei + EDG, P.A0);
    k_diag1<<<cdiv(N0, 256), 256>>>(P.A0);

    // ---- down path ----
    prep_deg(P.A0, N0, 0);
    gcn<20, 64>(P.A0, N0, 0, x_in, W0, b0, true, P.x0, nullptr, nullptr, p1);

    // level 1: sparse x sparse augment product (colsum pass kept)
    pool_level(P.A0, N0, K1, KP1, KD1, P.x0, P.perm0, P.A1, true, 1, 1);
    prep_deg(P.A1, K1, 1);
    gcn<64, 64>(P.A1, K1, 1, P.xp, W1, b1, true, P.x1, nullptr, nullptr, p2);

    // level 2: dense fp16 GEMM, split-K=2, degrees fused into epilogue
    pool_level(P.A1, K1, K2, KP2, KD2, P.x1, P.perm1, P.A2, false, 2, 2);
    gcn<64, 64>(P.A2, K2, 2, P.xp, W2, b2, true, P.x2, nullptr, nullptr, p3);

    // level 3: dense fp16 GEMM, degrees fused into epilogue
    pool_level(P.A2, K2, K3, KP3, KD3, P.x2, P.perm2, P.A3, false, 1, 3);
    // fused unpool: x2[perm2] += relu(conv(A3, xp))
    gcn<64, 64>(P.A3, K3, 3, P.xp, W3, b3, true, nullptr, P.x2, P.perm2);

    // ---- up path (degrees reused; unpool fused into fin) ----
    gcn<64, 64>(P.A2, K2, 2, P.x2, U0, c0, true, nullptr, P.x1, P.perm1);
    gcn<64, 64>(P.A1, K1, 1, P.x1, U1, c1, true, nullptr, P.x0, P.perm0);
    gcn<64, 20>(P.A0, N0, 0, P.x0, U2, c2, false, out);
}